// round 12
// baseline (speedup 1.0000x reference)
#include <cuda_runtime.h>
#include <cuda_bf16.h>

#define SEQ 2048
#define EMB 2048
#define NHEAD 32
#define HDIM 64
#define SCALING 0.125f

// Scratch buffers (allocation-free rule: __device__ globals)
__device__ float g_Q[SEQ * EMB];
__device__ float g_K[SEQ * EMB];
__device__ float g_V[SEQ * EMB];
__device__ float g_O[SEQ * EMB];

// ---------------------------------------------------------------------------
// helpers
// ---------------------------------------------------------------------------
__device__ __forceinline__ unsigned s2u(const void* p) {
    unsigned a;
    asm("{ .reg .u64 t; cvta.to.shared.u64 t, %1; cvt.u32.u64 %0, t; }"
        : "=r"(a) : "l"(p));
    return a;
}

// fp32 pair -> packed bf16x2 hi + packed bf16x2 residual (low half = a)
__device__ __forceinline__ void split2(float a, float b, unsigned& hi, unsigned& lo) {
    unsigned h;
    asm("cvt.rn.bf16x2.f32 %0, %1, %2;" : "=r"(h) : "f"(b), "f"(a));
    float ah = __uint_as_float(h << 16);
    float bh = __uint_as_float(h & 0xFFFF0000u);
    float ra = a - ah;
    float rb = b - bh;
    unsigned l;
    asm("cvt.rn.bf16x2.f32 %0, %1, %2;" : "=r"(l) : "f"(rb), "f"(ra));
    hi = h; lo = l;
}

#define MMA_BF16(C0, C1, C2, C3, A0, A1, A2, A3, B0, B1)                      \
    asm volatile(                                                             \
        "mma.sync.aligned.m16n8k16.row.col.f32.bf16.bf16.f32 "                \
        "{%0,%1,%2,%3}, {%4,%5,%6,%7}, {%8,%9}, {%0,%1,%2,%3};"               \
        : "+f"(C0), "+f"(C1), "+f"(C2), "+f"(C3)                              \
        : "r"(A0), "r"(A1), "r"(A2), "r"(A3), "r"(B0), "r"(B1))

#define LDSM_X4(R0, R1, R2, R3, ADDR)                                         \
    asm volatile("ldmatrix.sync.aligned.m8n8.x4.shared.b16 {%0,%1,%2,%3}, [%4];" \
        : "=r"(R0), "=r"(R1), "=r"(R2), "=r"(R3) : "r"(ADDR))

#define LDSM_X2(R0, R1, ADDR)                                                 \
    asm volatile("ldmatrix.sync.aligned.m8n8.x2.shared.b16 {%0,%1}, [%2];"    \
        : "=r"(R0), "=r"(R1) : "r"(ADDR))

#define LDSM_X2_T(R0, R1, ADDR)                                               \
    asm volatile("ldmatrix.sync.aligned.m8n8.x2.trans.shared.b16 {%0,%1}, [%2];" \
        : "=r"(R0), "=r"(R1) : "r"(ADDR))

#define STS_V2(ADDR, V0, V1)                                                  \
    asm volatile("st.shared.v2.b32 [%0], {%1,%2};" :: "r"(ADDR), "r"(V0), "r"(V1) : "memory")

// ---------------------------------------------------------------------------
// bf16x3 GEMM body (verified round 11) — Q and output projections.
// ---------------------------------------------------------------------------
#define ROW_B 80
#define TILE_B (128 * ROW_B)
#define STAGE_B (4 * TILE_B)
#define GEMM_SMEM (2 * STAGE_B)         // 81920
#define NCH 64

__device__ __forceinline__ void mma_gemm_body(
    const float* __restrict__ A, const float* __restrict__ B,
    const float* __restrict__ bias, float* __restrict__ C,
    float scale, int bxt, int byt, char* smem)
{
    const unsigned sb = s2u(smem);
    const int tid = threadIdx.x;
    const int wid = tid >> 5;
    const int lane = tid & 31;
    const int wm = wid & 1;
    const int wn = wid >> 1;
    const int m0 = byt * 128;
    const int n0 = bxt * 128;

    float acc[4][4][4];
#pragma unroll
    for (int i = 0; i < 4; i++)
#pragma unroll
        for (int j = 0; j < 4; j++)
#pragma unroll
            for (int r = 0; r < 4; r++) acc[i][j][r] = 0.f;

    float4 fa[4], fb[4];

    auto fetch = [&](int c) {
        const int k0 = c * 32;
#pragma unroll
        for (int u = 0; u < 4; u++) {
            int slot = tid + u * 256;
            int row = slot >> 3;
            int kq = (slot & 7) << 2;
            fa[u] = *(const float4*)&A[(size_t)(m0 + row) * EMB + k0 + kq];
            fb[u] = *(const float4*)&B[(size_t)(n0 + row) * EMB + k0 + kq];
        }
    };

    auto store_stage = [&](int s) {
        const unsigned base = sb + (unsigned)s * STAGE_B;
#pragma unroll
        for (int u = 0; u < 4; u++) {
            int slot = tid + u * 256;
            int row = slot >> 3;
            int kq = (slot & 7) << 2;
            unsigned off = (unsigned)(row * ROW_B + kq * 2);
            unsigned h01, l01, h23, l23;
            split2(fa[u].x, fa[u].y, h01, l01);
            split2(fa[u].z, fa[u].w, h23, l23);
            STS_V2(base + off, h01, h23);
            STS_V2(base + TILE_B + off, l01, l23);
            split2(fb[u].x, fb[u].y, h01, l01);
            split2(fb[u].z, fb[u].w, h23, l23);
            STS_V2(base + 2 * TILE_B + off, h01, h23);
            STS_V2(base + 3 * TILE_B + off, l01, l23);
        }
    };

    const unsigned a_rl = (unsigned)((lane & 7) + ((lane >> 3) & 1) * 8);
    const unsigned a_by = (unsigned)((lane >> 4) * 16);
    const unsigned b_rl = (unsigned)(lane & 7);
    const unsigned b_by = (unsigned)(((lane >> 3) & 1) * 16);

    fetch(0);
    store_stage(0);
    fetch(1);

#pragma unroll 1
    for (int c = 0; c < NCH; c++) {
        __syncthreads();
        if (c + 1 < NCH) store_stage((c + 1) & 1);
        if (c + 2 < NCH) fetch(c + 2);

        const unsigned abase = sb + (unsigned)(c & 1) * STAGE_B;
        const unsigned bbase = abase + 2 * TILE_B;

#pragma unroll
        for (int k16 = 0; k16 < 32; k16 += 16) {
            unsigned Ah[4][4], Al[4][4], Bh[4][2], Bl[4][2];
#pragma unroll
            for (int mt = 0; mt < 4; mt++) {
                unsigned ad = abase + (wm * 64 + mt * 16 + a_rl) * ROW_B
                            + (k16 * 2 + a_by);
                LDSM_X4(Ah[mt][0], Ah[mt][1], Ah[mt][2], Ah[mt][3], ad);
                LDSM_X4(Al[mt][0], Al[mt][1], Al[mt][2], Al[mt][3], ad + TILE_B);
            }
#pragma unroll
            for (int nt = 0; nt < 4; nt++) {
                unsigned bd = bbase + (wn * 32 + nt * 8 + b_rl) * ROW_B
                            + (k16 * 2 + b_by);
                LDSM_X2(Bh[nt][0], Bh[nt][1], bd);
                LDSM_X2(Bl[nt][0], Bl[nt][1], bd + TILE_B);
            }
#pragma unroll
            for (int mt = 0; mt < 4; mt++)
#pragma unroll
                for (int nt = 0; nt < 4; nt++) {
                    float* cc = acc[mt][nt];
                    MMA_BF16(cc[0], cc[1], cc[2], cc[3],
                             Ah[mt][0], Ah[mt][1], Ah[mt][2], Ah[mt][3],
                             Bh[nt][0], Bh[nt][1]);
                    MMA_BF16(cc[0], cc[1], cc[2], cc[3],
                             Ah[mt][0], Ah[mt][1], Ah[mt][2], Ah[mt][3],
                             Bl[nt][0], Bl[nt][1]);
                    MMA_BF16(cc[0], cc[1], cc[2], cc[3],
                             Al[mt][0], Al[mt][1], Al[mt][2], Al[mt][3],
                             Bh[nt][0], Bh[nt][1]);
                }
        }
    }

    const int g = lane >> 2;
    const int c2 = (lane & 3) * 2;
#pragma unroll
    for (int mt = 0; mt < 4; mt++) {
        const int r0 = m0 + wm * 64 + mt * 16 + g;
#pragma unroll
        for (int nt = 0; nt < 4; nt++) {
            const int col = n0 + wn * 32 + nt * 8 + c2;
            float2 bv = *(const float2*)&bias[col];
            float2 o0, o1;
            o0.x = (acc[mt][nt][0] + bv.x) * scale;
            o0.y = (acc[mt][nt][1] + bv.y) * scale;
            o1.x = (acc[mt][nt][2] + bv.x) * scale;
            o1.y = (acc[mt][nt][3] + bv.y) * scale;
            *(float2*)&C[(size_t)r0 * EMB + col] = o0;
            *(float2*)&C[(size_t)(r0 + 8) * EMB + col] = o1;
        }
    }
}

__global__ __launch_bounds__(256, 1)
void gemm_mma_kernel(const float* __restrict__ A, const float* __restrict__ B,
                     const float* __restrict__ bias, float* __restrict__ C,
                     float scale)
{
    extern __shared__ char smem[];
    mma_gemm_body(A, B, bias, C, scale, blockIdx.x, blockIdx.y, smem);
}

// ---------------------------------------------------------------------------
// QuotRem quantize over a 16-group held by two adjacent threads (8 vals each).
// fmax/fmin/exact ops -> bitwise-identical to the verified standalone kernel.
// ---------------------------------------------------------------------------
__device__ __forceinline__ void quant16_pair(float v[8]) {
    float mx = v[0], mn = v[0];
#pragma unroll
    for (int i = 1; i < 8; i++) {
        mx = fmaxf(mx, v[i]);
        mn = fminf(mn, v[i]);
    }
    mx = fmaxf(mx, __shfl_xor_sync(0xffffffff, mx, 1));
    mn = fminf(mn, __shfl_xor_sync(0xffffffff, mn, 1));
    float ma = fmaxf(fmaxf(mx, -mn), 1e-8f);

    float l2 = log2f(ma);
    float bflo = exp2f(floorf(l2));
    float bcei = exp2f(ceilf(l2));
    float base = (fabsf(ma - bflo) <= fabsf(bcei - ma)) ? bflo : bcei;
    base = fminf(fmaxf(base, 1.0f), 128.0f);

    float sign = (fabsf(mx) >= fabsf(mn)) ? 1.0f : -1.0f;
    float hb = 0.5f * base;
    float sb = sign * base;

    float qs[8], r[8];
    float mar = 0.f;
#pragma unroll
    for (int i = 0; i < 8; i++) {
        float q = (v[i] * sign >= hb) ? 1.0f : 0.0f;
        qs[i] = q * sb;
        r[i] = v[i] - qs[i];
        mar = fmaxf(mar, fabsf(r[i]));
    }
    mar = fmaxf(mar, __shfl_xor_sync(0xffffffff, mar, 1));
    mar = fmaxf(mar, 1e-8f);
    float sr = mar * (1.0f / 3.0f);

#pragma unroll
    for (int i = 0; i < 8; i++) {
        float rq = rintf(r[i] / sr);
        rq = fminf(fmaxf(rq, -4.0f), 3.0f);
        v[i] = qs[i] + rq * sr;
    }
}

// ---------------------------------------------------------------------------
// fp32 SIMT GEMM body + fused QuotRem quantize — K and V projections.
// Sequential fp32 FFMA accumulation is quantizer-pinned (rounds 4-10 data).
// Compute is bit-identical to the verified standalone kernel; the quantize
// is applied in-register before the store (same values the standalone
// quantize kernel would have read back).
// ---------------------------------------------------------------------------
#define BM 128
#define BN 128
#define BK 16
#define GK 2048
#define SIMT_SMEM_A 0
#define SIMT_SMEM_B (BK * BM * 4)

__device__ __forceinline__ void simt_gemm_quant_body(
    const float* __restrict__ A, const float* __restrict__ B,
    const float* __restrict__ bias, float* __restrict__ C,
    int bxt, int byt, char* smem)
{
    float* As = (float*)(smem + SIMT_SMEM_A);   // [BK][BM]
    float* Bs = (float*)(smem + SIMT_SMEM_B);   // [BK][BN]

    const int tid = threadIdx.x;
    const int tx = tid & 15;
    const int ty = tid >> 4;
    const int m0 = byt * BM;
    const int n0 = bxt * BN;

    float acc[8][8];
#pragma unroll
    for (int i = 0; i < 8; i++)
#pragma unroll
        for (int j = 0; j < 8; j++) acc[i][j] = 0.f;

    for (int kt = 0; kt < GK; kt += BK) {
#pragma unroll
        for (int u = 0; u < 2; u++) {
            int i = tid + u * 256;
            int row = i >> 2;
            int kq = (i & 3) << 2;
            float4 a = *(const float4*)&A[(size_t)(m0 + row) * GK + kt + kq];
            As[(kq + 0) * BM + row] = a.x; As[(kq + 1) * BM + row] = a.y;
            As[(kq + 2) * BM + row] = a.z; As[(kq + 3) * BM + row] = a.w;
            float4 b = *(const float4*)&B[(size_t)(n0 + row) * GK + kt + kq];
            Bs[(kq + 0) * BN + row] = b.x; Bs[(kq + 1) * BN + row] = b.y;
            Bs[(kq + 2) * BN + row] = b.z; Bs[(kq + 3) * BN + row] = b.w;
        }
        __syncthreads();

#pragma unroll
        for (int k = 0; k < BK; k++) {
            float4 a0 = *(const float4*)&As[k * BM + ty * 8];
            float4 a1 = *(const float4*)&As[k * BM + ty * 8 + 4];
            float4 b0 = *(const float4*)&Bs[k * BN + tx * 8];
            float4 b1 = *(const float4*)&Bs[k * BN + tx * 8 + 4];
            float ar[8] = {a0.x, a0.y, a0.z, a0.w, a1.x, a1.y, a1.z, a1.w};
            float br[8] = {b0.x, b0.y, b0.z, b0.w, b1.x, b1.y, b1.z, b1.w};
#pragma unroll
            for (int i = 0; i < 8; i++)
#pragma unroll
                for (int j = 0; j < 8; j++)
                    acc[i][j] += ar[i] * br[j];
        }
        __syncthreads();
    }

    float4 bv0 = *(const float4*)&bias[n0 + tx * 8];
    float4 bv1 = *(const float4*)&bias[n0 + tx * 8 + 4];
    float bb[8] = {bv0.x, bv0.y, bv0.z, bv0.w, bv1.x, bv1.y, bv1.z, bv1.w};

#pragma unroll
    for (int i = 0; i < 8; i++) {
        int row = m0 + ty * 8 + i;
        float v[8];
#pragma unroll
        for (int j = 0; j < 8; j++) v[j] = acc[i][j] + bb[j];
        quant16_pair(v);                   // fused QuotRem quantize
        float4 o0, o1;
        o0.x = v[0]; o0.y = v[1]; o0.z = v[2]; o0.w = v[3];
        o1.x = v[4]; o1.y = v[5]; o1.z = v[6]; o1.w = v[7];
        *(float4*)&C[(size_t)row * GK + n0 + tx * 8] = o0;
        *(float4*)&C[(size_t)row * GK + n0 + tx * 8 + 4] = o1;
    }
}

// ---------------------------------------------------------------------------
// Fused QKV projection kernel. Role = blockIdx.x % 3 (0=K, 1=V, 2=Q),
// interleaved so FMA-bound (K/V) and tensor-bound (Q) CTAs co-reside and
// overlap on disjoint pipes.
// ---------------------------------------------------------------------------
__global__ __launch_bounds__(256)
void qkv_fused_kernel(
    const float* __restrict__ X,
    const float* __restrict__ Wq, const float* __restrict__ bq, float* __restrict__ Qo,
    const float* __restrict__ Wk, const float* __restrict__ bk, float* __restrict__ Ko,
    const float* __restrict__ Wv, const float* __restrict__ bv, float* __restrict__ Vo)
{
    extern __shared__ char smem[];
    const int role = (int)(blockIdx.x % 3);
    const int bxt = (int)(blockIdx.x / 3);
    const int byt = (int)blockIdx.y;

    if (role == 0) {
        simt_gemm_quant_body(X, Wk, bk, Ko, bxt, byt, smem);
    } else if (role == 1) {
        simt_gemm_quant_body(X, Wv, bv, Vo, bxt, byt, smem);
    } else {
        mma_gemm_body(X, Wq, bq, Qo, SCALING, bxt, byt, smem);
    }
}

// ---------------------------------------------------------------------------
// MMA causal flash attention (verified round 7)
// ---------------------------------------------------------------------------
#define FA_ROW 144
#define FA_TILE (64 * FA_ROW)
#define FA_STAGE (4 * FA_TILE)
#define FA_SMEM (2 * FA_STAGE)

__global__ __launch_bounds__(256, 1)
void flash_attn_mma_kernel(const float* __restrict__ Q, const float* __restrict__ K,
                           const float* __restrict__ V, float* __restrict__ O)
{
    extern __shared__ char smem[];
    const unsigned sb = s2u(smem);
    const int tid = threadIdx.x;
    const int wid = tid >> 5;
    const int lane = tid & 31;
    const int head = blockIdx.y;
    const int bx = (int)gridDim.x - 1 - (int)blockIdx.x;
    const int r0 = bx * 128;
    const int hb = head * HDIM;
    const int rw = r0 + wid * 16;
    const int g = lane >> 2;
    const int t = lane & 3;

#pragma unroll
    for (int u = 0; u < 8; u++) {
        int slot = tid + u * 256;
        int row = slot >> 4;
        int dq = (slot & 15) << 2;
        float4 v = *(const float4*)&Q[(size_t)(r0 + row) * EMB + hb + dq];
        unsigned h01, l01, h23, l23;
        split2(v.x, v.y, h01, l01);
        split2(v.z, v.w, h23, l23);
        unsigned off = (unsigned)(row * FA_ROW + dq * 2);
        STS_V2(sb + off, h01, h23);
        STS_V2(sb + 18432u + off, l01, l23);
    }
    __syncthreads();

    const unsigned a_rl = (unsigned)((lane & 7) + ((lane >> 3) & 1) * 8);
    const unsigned a_by = (unsigned)((lane >> 4) * 16);
    unsigned QH[4][4], QL[4][4];
#pragma unroll
    for (int kc = 0; kc < 4; kc++) {
        unsigned ad = sb + (wid * 16 + a_rl) * FA_ROW + kc * 32 + a_by;
        LDSM_X4(QH[kc][0], QH[kc][1], QH[kc][2], QH[kc][3], ad);
        LDSM_X4(QL[kc][0], QL[kc][1], QL[kc][2], QL[kc][3], ad + 18432u);
    }
    __syncthreads();

    float o[8][4];
#pragma unroll
    for (int j = 0; j < 8; j++)
#pragma unroll
        for (int r = 0; r < 4; r++) o[j][r] = 0.f;
    float m0r = -1e30f, m1r = -1e30f, l0 = 0.f, l1 = 0.f;

    const int ntiles = 2 * bx + 2;
    float4 fk[4], fv[4];

    auto fetchKV = [&](int tI) {
        const int c0 = tI * 64;
#pragma unroll
        for (int u = 0; u < 4; u++) {
            int slot = tid + u * 256;
            int kr = slot >> 4;
            int dq = (slot & 15) << 2;
            fk[u] = *(const float4*)&K[(size_t)(c0 + kr) * EMB + hb + dq];
            fv[u] = *(const float4*)&V[(size_t)(c0 + kr) * EMB + hb + dq];
        }
    };
    auto storeKV = [&](int s) {
        const unsigned base = sb + (unsigned)s * FA_STAGE;
#pragma unroll
        for (int u = 0; u < 4; u++) {
            int slot = tid + u * 256;
            int kr = slot >> 4;
            int dq = (slot & 15) << 2;
            unsigned off = (unsigned)(kr * FA_ROW + dq * 2);
            unsigned h01, l01, h23, l23;
            split2(fk[u].x, fk[u].y, h01, l01);
            split2(fk[u].z, fk[u].w, h23, l23);
            STS_V2(base + off, h01, h23);
            STS_V2(base + FA_TILE + off, l01, l23);
            split2(fv[u].x, fv[u].y, h01, l01);
            split2(fv[u].z, fv[u].w, h23, l23);
            STS_V2(base + 2 * FA_TILE + off, h01, h23);
            STS_V2(base + 3 * FA_TILE + off, l01, l23);
        }
    };

    fetchKV(0);
    storeKV(0);
    if (ntiles > 1) fetchKV(1);

#pragma unroll 1
    for (int c = 0; c < ntiles; c++) {
        __syncthreads();
        if (c + 1 < ntiles) storeKV((c + 1) & 1);
        if (c + 2 < ntiles) fetchKV(c + 2);

        const int c0 = c * 64;
        if (c0 <= rw + 15) {
            const unsigned kb = sb + (unsigned)(c & 1) * FA_STAGE;

            float s[8][4];
#pragma unroll
            for (int j = 0; j < 8; j++)
#pragma unroll
                for (int r = 0; r < 4; r++) s[j][r] = 0.f;

#pragma unroll
            for (int j = 0; j < 8; j++) {
                const unsigned bd = kb + (8 * j + (lane & 7)) * FA_ROW
                                  + ((lane >> 3) & 1) * 16;
#pragma unroll
                for (int kc = 0; kc < 4; kc++) {
                    unsigned bh0, bh1, bl0, bl1;
                    LDSM_X2(bh0, bh1, bd + kc * 32);
                    LDSM_X2(bl0, bl1, bd + kc * 32 + FA_TILE);
                    MMA_BF16(s[j][0], s[j][1], s[j][2], s[j][3],
                             QH[kc][0], QH[kc][1], QH[kc][2], QH[kc][3], bh0, bh1);
                    MMA_BF16(s[j][0], s[j][1], s[j][2], s[j][3],
                             QH[kc][0], QH[kc][1], QH[kc][2], QH[kc][3], bl0, bl1);
                    MMA_BF16(s[j][0], s[j][1], s[j][2], s[j][3],
                             QL[kc][0], QL[kc][1], QL[kc][2], QL[kc][3], bh0, bh1);
                }
            }

            if (c0 + 63 > rw) {
                const int rA = rw + g;
                const int rB = rw + g + 8;
#pragma unroll
                for (int j = 0; j < 8; j++) {
                    int col = c0 + 8 * j + 2 * t;
                    if (col > rA)     s[j][0] = -1e30f;
                    if (col + 1 > rA) s[j][1] = -1e30f;
                    if (col > rB)     s[j][2] = -1e30f;
                    if (col + 1 > rB) s[j][3] = -1e30f;
                }
            }

            float t0 = -1e30f, t1 = -1e30f;
#pragma unroll
            for (int j = 0; j < 8; j++) {
                t0 = fmaxf(t0, fmaxf(s[j][0], s[j][1]));
                t1 = fmaxf(t1, fmaxf(s[j][2], s[j][3]));
            }
            t0 = fmaxf(t0, __shfl_xor_sync(0xffffffff, t0, 1));
            t0 = fmaxf(t0, __shfl_xor_sync(0xffffffff, t0, 2));
            t1 = fmaxf(t1, __shfl_xor_sync(0xffffffff, t1, 1));
            t1 = fmaxf(t1, __shfl_xor_sync(0xffffffff, t1, 2));
            const float mn0 = fmaxf(m0r, t0);
            const float mn1 = fmaxf(m1r, t1);
            const float sc0 = __expf(m0r - mn0);
            const float sc1 = __expf(m1r - mn1);
            float sum0 = 0.f, sum1 = 0.f;
#pragma unroll
            for (int j = 0; j < 8; j++) {
                float p0 = __expf(s[j][0] - mn0);
                float p1 = __expf(s[j][1] - mn0);
                float p2 = __expf(s[j][2] - mn1);
                float p3 = __expf(s[j][3] - mn1);
                s[j][0] = p0; s[j][1] = p1; s[j][2] = p2; s[j][3] = p3;
                sum0 += p0 + p1;
                sum1 += p2 + p3;
            }
            sum0 += __shfl_xor_sync(0xffffffff, sum0, 1);
            sum0 += __shfl_xor_sync(0xffffffff, sum0, 2);
            sum1 += __shfl_xor_sync(0xffffffff, sum1, 1);
            sum1 += __shfl_xor_sync(0xffffffff, sum1, 2);
            l0 = l0 * sc0 + sum0;
            l1 = l1 * sc1 + sum1;
            m0r = mn0; m1r = mn1;
#pragma unroll
            for (int j = 0; j < 8; j++) {
                o[j][0] *= sc0; o[j][1] *= sc0;
                o[j][2] *= sc1; o[j][3] *= sc1;
            }

#pragma unroll
            for (int kc2 = 0; kc2 < 4; kc2++) {
                unsigned ph[4], pl[4];
                split2(s[2 * kc2][0],     s[2 * kc2][1],     ph[0], pl[0]);
                split2(s[2 * kc2][2],     s[2 * kc2][3],     ph[1], pl[1]);
                split2(s[2 * kc2 + 1][0], s[2 * kc2 + 1][1], ph[2], pl[2]);
                split2(s[2 * kc2 + 1][2], s[2 * kc2 + 1][3], ph[3], pl[3]);
                const unsigned vrow = kb + 2 * FA_TILE
                                    + (16 * kc2 + (lane & 15)) * FA_ROW;
#pragma unroll
                for (int j = 0; j < 8; j++) {
                    unsigned v0, v1, w0, w1;
                    LDSM_X2_T(v0, v1, vrow + j * 16);
                    LDSM_X2_T(w0, w1, vrow + j * 16 + FA_TILE);
                    MMA_BF16(o[j][0], o[j][1], o[j][2], o[j][3],
                             ph[0], ph[1], ph[2], ph[3], v0, v1);
                    MMA_BF16(o[j][0], o[j][1], o[j][2], o[j][3],
                             ph[0], ph[1], ph[2], ph[3], w0, w1);
                    MMA_BF16(o[j][0], o[j][1], o[j][2], o[j][3],
                             pl[0], pl[1], pl[2], pl[3], v0, v1);
                }
            }
        }
    }

    const float inv0 = 1.0f / l0;
    const float inv1 = 1.0f / l1;
    const int rA = rw + g;
    const int rB = rw + g + 8;
#pragma unroll
    for (int j = 0; j < 8; j++) {
        const int col = hb + 8 * j + 2 * t;
        float2 oa, ob;
        oa.x = o[j][0] * inv0; oa.y = o[j][1] * inv0;
        ob.x = o[j][2] * inv1; ob.y = o[j][3] * inv1;
        *(float2*)&O[(size_t)rA * EMB + col] = oa;
        *(float2*)&O[(size_t)rB * EMB + col] = ob;
    }
}

// ---------------------------------------------------------------------------
// Launch
// ---------------------------------------------------------------------------
extern "C" void kernel_launch(void* const* d_in, const int* in_sizes, int n_in,
                              void* d_out, int out_size)
{
    const float* X  = (const float*)d_in[0];
    const float* Wq = (const float*)d_in[1];
    const float* bq = (const float*)d_in[2];
    const float* Wk = (const float*)d_in[3];
    const float* bk = (const float*)d_in[4];
    const float* Wv = (const float*)d_in[5];
    const float* bv = (const float*)d_in[6];
    const float* Wo = (const float*)d_in[7];
    const float* bo = (const float*)d_in[8];
    float* out = (float*)d_out;

    void *pQ, *pK, *pV, *pO;
    cudaGetSymbolAddress(&pQ, g_Q);
    cudaGetSymbolAddress(&pK, g_K);
    cudaGetSymbolAddress(&pV, g_V);
    cudaGetSymbolAddress(&pO, g_O);
    float* Qb = (float*)pQ;
    float* Kb = (float*)pK;
    float* Vb = (float*)pV;
    float* Ob = (float*)pO;

    cudaFuncSetAttribute(qkv_fused_kernel,
                         cudaFuncAttributeMaxDynamicSharedMemorySize, GEMM_SMEM);
    cudaFuncSetAttribute(gemm_mma_kernel,
                         cudaFuncAttributeMaxDynamicSharedMemorySize, GEMM_SMEM);
    cudaFuncSetAttribute(flash_attn_mma_kernel,
                         cudaFuncAttributeMaxDynamicSharedMemorySize, FA_SMEM);

    // Fused Q/K/V projections (+ quantize in K/V epilogues), roles interleaved
    qkv_fused_kernel<<<dim3(3 * (EMB / 128), SEQ / 128), 256, GEMM_SMEM>>>(
        X, Wq, bq, Qb, Wk, bk, Kb, Wv, bv, Vb);

    flash_attn_mma_kernel<<<dim3(SEQ / 128, NHEAD), 256, FA_SMEM>>>(Qb, Kb, Vb, Ob);

    // Output projection: bf16x3 mma (verified)
    gemm_mma_kernel<<<dim3(EMB / 128, SEQ / 128), 256, GEMM_SMEM>>>(Ob, Wo, bo, out, 1.0f);
}

// round 14
// speedup vs baseline: 1.0888x; 1.0888x over previous
#include <cuda_runtime.h>
#include <cuda_bf16.h>

#define SEQ 2048
#define EMB 2048
#define NHEAD 32
#define HDIM 64
#define SCALING 0.125f

// Scratch buffers (allocation-free rule: __device__ globals)
__device__ float g_Q[SEQ * EMB];
__device__ float g_K[SEQ * EMB];
__device__ float g_V[SEQ * EMB];
__device__ float g_O[SEQ * EMB];

// ---------------------------------------------------------------------------
// helpers
// ---------------------------------------------------------------------------
__device__ __forceinline__ unsigned s2u(const void* p) {
    unsigned a;
    asm("{ .reg .u64 t; cvta.to.shared.u64 t, %1; cvt.u32.u64 %0, t; }"
        : "=r"(a) : "l"(p));
    return a;
}

// fp32 pair -> packed bf16x2 hi + packed bf16x2 residual (low half = a)
__device__ __forceinline__ void split2(float a, float b, unsigned& hi, unsigned& lo) {
    unsigned h;
    asm("cvt.rn.bf16x2.f32 %0, %1, %2;" : "=r"(h) : "f"(b), "f"(a));
    float ah = __uint_as_float(h << 16);
    float bh = __uint_as_float(h & 0xFFFF0000u);
    float ra = a - ah;
    float rb = b - bh;
    unsigned l;
    asm("cvt.rn.bf16x2.f32 %0, %1, %2;" : "=r"(l) : "f"(rb), "f"(ra));
    hi = h; lo = l;
}

#define MMA_BF16(C0, C1, C2, C3, A0, A1, A2, A3, B0, B1)                      \
    asm volatile(                                                             \
        "mma.sync.aligned.m16n8k16.row.col.f32.bf16.bf16.f32 "                \
        "{%0,%1,%2,%3}, {%4,%5,%6,%7}, {%8,%9}, {%0,%1,%2,%3};"               \
        : "+f"(C0), "+f"(C1), "+f"(C2), "+f"(C3)                              \
        : "r"(A0), "r"(A1), "r"(A2), "r"(A3), "r"(B0), "r"(B1))

#define LDSM_X4(R0, R1, R2, R3, ADDR)                                         \
    asm volatile("ldmatrix.sync.aligned.m8n8.x4.shared.b16 {%0,%1,%2,%3}, [%4];" \
        : "=r"(R0), "=r"(R1), "=r"(R2), "=r"(R3) : "r"(ADDR))

#define LDSM_X2(R0, R1, ADDR)                                                 \
    asm volatile("ldmatrix.sync.aligned.m8n8.x2.shared.b16 {%0,%1}, [%2];"    \
        : "=r"(R0), "=r"(R1) : "r"(ADDR))

#define LDSM_X2_T(R0, R1, ADDR)                                               \
    asm volatile("ldmatrix.sync.aligned.m8n8.x2.trans.shared.b16 {%0,%1}, [%2];" \
        : "=r"(R0), "=r"(R1) : "r"(ADDR))

#define STS_V2(ADDR, V0, V1)                                                  \
    asm volatile("st.shared.v2.b32 [%0], {%1,%2};" :: "r"(ADDR), "r"(V0), "r"(V1) : "memory")

// ---------------------------------------------------------------------------
// bf16x3 GEMM (verified round 11) — Q and output projections.
// ---------------------------------------------------------------------------
#define ROW_B 80
#define TILE_B (128 * ROW_B)
#define STAGE_B (4 * TILE_B)
#define GEMM_SMEM (2 * STAGE_B)         // 81920
#define NCH 64

__global__ __launch_bounds__(256, 1)
void gemm_mma_kernel(const float* __restrict__ A, const float* __restrict__ B,
                     const float* __restrict__ bias, float* __restrict__ C,
                     float scale)
{
    extern __shared__ char smem[];
    const unsigned sb = s2u(smem);
    const int tid = threadIdx.x;
    const int wid = tid >> 5;
    const int lane = tid & 31;
    const int wm = wid & 1;
    const int wn = wid >> 1;
    const int m0 = blockIdx.y * 128;
    const int n0 = blockIdx.x * 128;

    float acc[4][4][4];
#pragma unroll
    for (int i = 0; i < 4; i++)
#pragma unroll
        for (int j = 0; j < 4; j++)
#pragma unroll
            for (int r = 0; r < 4; r++) acc[i][j][r] = 0.f;

    float4 fa[4], fb[4];

    auto fetch = [&](int c) {
        const int k0 = c * 32;
#pragma unroll
        for (int u = 0; u < 4; u++) {
            int slot = tid + u * 256;
            int row = slot >> 3;
            int kq = (slot & 7) << 2;
            fa[u] = *(const float4*)&A[(size_t)(m0 + row) * EMB + k0 + kq];
            fb[u] = *(const float4*)&B[(size_t)(n0 + row) * EMB + k0 + kq];
        }
    };

    auto store_stage = [&](int s) {
        const unsigned base = sb + (unsigned)s * STAGE_B;
#pragma unroll
        for (int u = 0; u < 4; u++) {
            int slot = tid + u * 256;
            int row = slot >> 3;
            int kq = (slot & 7) << 2;
            unsigned off = (unsigned)(row * ROW_B + kq * 2);
            unsigned h01, l01, h23, l23;
            split2(fa[u].x, fa[u].y, h01, l01);
            split2(fa[u].z, fa[u].w, h23, l23);
            STS_V2(base + off, h01, h23);
            STS_V2(base + TILE_B + off, l01, l23);
            split2(fb[u].x, fb[u].y, h01, l01);
            split2(fb[u].z, fb[u].w, h23, l23);
            STS_V2(base + 2 * TILE_B + off, h01, h23);
            STS_V2(base + 3 * TILE_B + off, l01, l23);
        }
    };

    const unsigned a_rl = (unsigned)((lane & 7) + ((lane >> 3) & 1) * 8);
    const unsigned a_by = (unsigned)((lane >> 4) * 16);
    const unsigned b_rl = (unsigned)(lane & 7);
    const unsigned b_by = (unsigned)(((lane >> 3) & 1) * 16);

    fetch(0);
    store_stage(0);
    fetch(1);

#pragma unroll 1
    for (int c = 0; c < NCH; c++) {
        __syncthreads();
        if (c + 1 < NCH) store_stage((c + 1) & 1);
        if (c + 2 < NCH) fetch(c + 2);

        const unsigned abase = sb + (unsigned)(c & 1) * STAGE_B;
        const unsigned bbase = abase + 2 * TILE_B;

#pragma unroll
        for (int k16 = 0; k16 < 32; k16 += 16) {
            unsigned Ah[4][4], Al[4][4], Bh[4][2], Bl[4][2];
#pragma unroll
            for (int mt = 0; mt < 4; mt++) {
                unsigned ad = abase + (wm * 64 + mt * 16 + a_rl) * ROW_B
                            + (k16 * 2 + a_by);
                LDSM_X4(Ah[mt][0], Ah[mt][1], Ah[mt][2], Ah[mt][3], ad);
                LDSM_X4(Al[mt][0], Al[mt][1], Al[mt][2], Al[mt][3], ad + TILE_B);
            }
#pragma unroll
            for (int nt = 0; nt < 4; nt++) {
                unsigned bd = bbase + (wn * 32 + nt * 8 + b_rl) * ROW_B
                            + (k16 * 2 + b_by);
                LDSM_X2(Bh[nt][0], Bh[nt][1], bd);
                LDSM_X2(Bl[nt][0], Bl[nt][1], bd + TILE_B);
            }
#pragma unroll
            for (int mt = 0; mt < 4; mt++)
#pragma unroll
                for (int nt = 0; nt < 4; nt++) {
                    float* cc = acc[mt][nt];
                    MMA_BF16(cc[0], cc[1], cc[2], cc[3],
                             Ah[mt][0], Ah[mt][1], Ah[mt][2], Ah[mt][3],
                             Bh[nt][0], Bh[nt][1]);
                    MMA_BF16(cc[0], cc[1], cc[2], cc[3],
                             Ah[mt][0], Ah[mt][1], Ah[mt][2], Ah[mt][3],
                             Bl[nt][0], Bl[nt][1]);
                    MMA_BF16(cc[0], cc[1], cc[2], cc[3],
                             Al[mt][0], Al[mt][1], Al[mt][2], Al[mt][3],
                             Bh[nt][0], Bh[nt][1]);
                }
        }
    }

    const int g = lane >> 2;
    const int c2 = (lane & 3) * 2;
#pragma unroll
    for (int mt = 0; mt < 4; mt++) {
        const int r0 = m0 + wm * 64 + mt * 16 + g;
#pragma unroll
        for (int nt = 0; nt < 4; nt++) {
            const int col = n0 + wn * 32 + nt * 8 + c2;
            float2 bv = *(const float2*)&bias[col];
            float2 o0, o1;
            o0.x = (acc[mt][nt][0] + bv.x) * scale;
            o0.y = (acc[mt][nt][1] + bv.y) * scale;
            o1.x = (acc[mt][nt][2] + bv.x) * scale;
            o1.y = (acc[mt][nt][3] + bv.y) * scale;
            *(float2*)&C[(size_t)r0 * EMB + col] = o0;
            *(float2*)&C[(size_t)(r0 + 8) * EMB + col] = o1;
        }
    }
}

// ---------------------------------------------------------------------------
// QuotRem quantize over a 16-group held by two adjacent threads (8 vals each).
// VERIFIED bitwise-identical to the standalone kernel (round 12 rel_err match).
// ---------------------------------------------------------------------------
__device__ __forceinline__ void quant16_pair(float v[8]) {
    float mx = v[0], mn = v[0];
#pragma unroll
    for (int i = 1; i < 8; i++) {
        mx = fmaxf(mx, v[i]);
        mn = fminf(mn, v[i]);
    }
    mx = fmaxf(mx, __shfl_xor_sync(0xffffffff, mx, 1));
    mn = fminf(mn, __shfl_xor_sync(0xffffffff, mn, 1));
    float ma = fmaxf(fmaxf(mx, -mn), 1e-8f);

    float l2 = log2f(ma);
    float bflo = exp2f(floorf(l2));
    float bcei = exp2f(ceilf(l2));
    float base = (fabsf(ma - bflo) <= fabsf(bcei - ma)) ? bflo : bcei;
    base = fminf(fmaxf(base, 1.0f), 128.0f);

    float sign = (fabsf(mx) >= fabsf(mn)) ? 1.0f : -1.0f;
    float hb = 0.5f * base;
    float sb = sign * base;

    float qs[8], r[8];
    float mar = 0.f;
#pragma unroll
    for (int i = 0; i < 8; i++) {
        float q = (v[i] * sign >= hb) ? 1.0f : 0.0f;
        qs[i] = q * sb;
        r[i] = v[i] - qs[i];
        mar = fmaxf(mar, fabsf(r[i]));
    }
    mar = fmaxf(mar, __shfl_xor_sync(0xffffffff, mar, 1));
    mar = fmaxf(mar, 1e-8f);
    float sr = mar * (1.0f / 3.0f);

#pragma unroll
    for (int i = 0; i < 8; i++) {
        float rq = rintf(r[i] / sr);
        rq = fminf(fmaxf(rq, -4.0f), 3.0f);
        v[i] = qs[i] + rq * sr;
    }
}

// ---------------------------------------------------------------------------
// fp32 SIMT GEMM + fused QuotRem quantize — K and V in ONE launch
// (blockIdx.z selects role; identical body -> no register inflation).
// Sequential fp32 FFMA accumulation is quantizer-pinned; ~93% of the
// FFMA-3reg roofline. Do not replace the math.
// ---------------------------------------------------------------------------
#define BM 128
#define BN 128
#define BK 16
#define GK 2048

__global__ __launch_bounds__(256)
void kv_gemm_quant_kernel(
    const float* __restrict__ X,
    const float* __restrict__ Wk, const float* __restrict__ bk, float* __restrict__ Ko,
    const float* __restrict__ Wv, const float* __restrict__ bv, float* __restrict__ Vo)
{
    __shared__ float As[BK][BM];
    __shared__ float Bs[BK][BN];

    const float* B   = (blockIdx.z == 0) ? Wk : Wv;
    const float* bias = (blockIdx.z == 0) ? bk : bv;
    float* C          = (blockIdx.z == 0) ? Ko : Vo;

    const int tid = threadIdx.x;
    const int tx = tid & 15;
    const int ty = tid >> 4;
    const int m0 = blockIdx.y * BM;
    const int n0 = blockIdx.x * BN;

    float acc[8][8];
#pragma unroll
    for (int i = 0; i < 8; i++)
#pragma unroll
        for (int j = 0; j < 8; j++) acc[i][j] = 0.f;

    for (int kt = 0; kt < GK; kt += BK) {
#pragma unroll
        for (int u = 0; u < 2; u++) {
            int i = tid + u * 256;
            int row = i >> 2;
            int kq = (i & 3) << 2;
            float4 a = *(const float4*)&X[(size_t)(m0 + row) * GK + kt + kq];
            As[kq + 0][row] = a.x; As[kq + 1][row] = a.y;
            As[kq + 2][row] = a.z; As[kq + 3][row] = a.w;
            float4 b = *(const float4*)&B[(size_t)(n0 + row) * GK + kt + kq];
            Bs[kq + 0][row] = b.x; Bs[kq + 1][row] = b.y;
            Bs[kq + 2][row] = b.z; Bs[kq + 3][row] = b.w;
        }
        __syncthreads();

#pragma unroll
        for (int k = 0; k < BK; k++) {
            float4 a0 = *(const float4*)&As[k][ty * 8];
            float4 a1 = *(const float4*)&As[k][ty * 8 + 4];
            float4 b0 = *(const float4*)&Bs[k][tx * 8];
            float4 b1 = *(const float4*)&Bs[k][tx * 8 + 4];
            float ar[8] = {a0.x, a0.y, a0.z, a0.w, a1.x, a1.y, a1.z, a1.w};
            float br[8] = {b0.x, b0.y, b0.z, b0.w, b1.x, b1.y, b1.z, b1.w};
#pragma unroll
            for (int i = 0; i < 8; i++)
#pragma unroll
                for (int j = 0; j < 8; j++)
                    acc[i][j] += ar[i] * br[j];
        }
        __syncthreads();
    }

    float4 bv0 = *(const float4*)&bias[n0 + tx * 8];
    float4 bv1 = *(const float4*)&bias[n0 + tx * 8 + 4];
    float bb[8] = {bv0.x, bv0.y, bv0.z, bv0.w, bv1.x, bv1.y, bv1.z, bv1.w};

#pragma unroll
    for (int i = 0; i < 8; i++) {
        int row = m0 + ty * 8 + i;
        float v[8];
#pragma unroll
        for (int j = 0; j < 8; j++) v[j] = acc[i][j] + bb[j];
        quant16_pair(v);                   // fused QuotRem quantize (verified)
        float4 o0, o1;
        o0.x = v[0]; o0.y = v[1]; o0.z = v[2]; o0.w = v[3];
        o1.x = v[4]; o1.y = v[5]; o1.z = v[6]; o1.w = v[7];
        *(float4*)&C[(size_t)row * GK + n0 + tx * 8] = o0;
        *(float4*)&C[(size_t)row * GK + n0 + tx * 8 + 4] = o1;
    }
}

// ---------------------------------------------------------------------------
// MMA causal flash attention (verified round 7)
// ---------------------------------------------------------------------------
#define FA_ROW 144
#define FA_TILE (64 * FA_ROW)
#define FA_STAGE (4 * FA_TILE)
#define FA_SMEM (2 * FA_STAGE)

__global__ __launch_bounds__(256, 1)
void flash_attn_mma_kernel(const float* __restrict__ Q, const float* __restrict__ K,
                           const float* __restrict__ V, float* __restrict__ O)
{
    extern __shared__ char smem[];
    const unsigned sb = s2u(smem);
    const int tid = threadIdx.x;
    const int wid = tid >> 5;
    const int lane = tid & 31;
    const int head = blockIdx.y;
    const int bx = (int)gridDim.x - 1 - (int)blockIdx.x;
    const int r0 = bx * 128;
    const int hb = head * HDIM;
    const int rw = r0 + wid * 16;
    const int g = lane >> 2;
    const int t = lane & 3;

#pragma unroll
    for (int u = 0; u < 8; u++) {
        int slot = tid + u * 256;
        int row = slot >> 4;
        int dq = (slot & 15) << 2;
        float4 v = *(const float4*)&Q[(size_t)(r0 + row) * EMB + hb + dq];
        unsigned h01, l01, h23, l23;
        split2(v.x, v.y, h01, l01);
        split2(v.z, v.w, h23, l23);
        unsigned off = (unsigned)(row * FA_ROW + dq * 2);
        STS_V2(sb + off, h01, h23);
        STS_V2(sb + 18432u + off, l01, l23);
    }
    __syncthreads();

    const unsigned a_rl = (unsigned)((lane & 7) + ((lane >> 3) & 1) * 8);
    const unsigned a_by = (unsigned)((lane >> 4) * 16);
    unsigned QH[4][4], QL[4][4];
#pragma unroll
    for (int kc = 0; kc < 4; kc++) {
        unsigned ad = sb + (wid * 16 + a_rl) * FA_ROW + kc * 32 + a_by;
        LDSM_X4(QH[kc][0], QH[kc][1], QH[kc][2], QH[kc][3], ad);
        LDSM_X4(QL[kc][0], QL[kc][1], QL[kc][2], QL[kc][3], ad + 18432u);
    }
    __syncthreads();

    float o[8][4];
#pragma unroll
    for (int j = 0; j < 8; j++)
#pragma unroll
        for (int r = 0; r < 4; r++) o[j][r] = 0.f;
    float m0r = -1e30f, m1r = -1e30f, l0 = 0.f, l1 = 0.f;

    const int ntiles = 2 * bx + 2;
    float4 fk[4], fv[4];

    auto fetchKV = [&](int tI) {
        const int c0 = tI * 64;
#pragma unroll
        for (int u = 0; u < 4; u++) {
            int slot = tid + u * 256;
            int kr = slot >> 4;
            int dq = (slot & 15) << 2;
            fk[u] = *(const float4*)&K[(size_t)(c0 + kr) * EMB + hb + dq];
            fv[u] = *(const float4*)&V[(size_t)(c0 + kr) * EMB + hb + dq];
        }
    };
    auto storeKV = [&](int s) {
        const unsigned base = sb + (unsigned)s * FA_STAGE;
#pragma unroll
        for (int u = 0; u < 4; u++) {
            int slot = tid + u * 256;
            int kr = slot >> 4;
            int dq = (slot & 15) << 2;
            unsigned off = (unsigned)(kr * FA_ROW + dq * 2);
            unsigned h01, l01, h23, l23;
            split2(fk[u].x, fk[u].y, h01, l01);
            split2(fk[u].z, fk[u].w, h23, l23);
            STS_V2(base + off, h01, h23);
            STS_V2(base + FA_TILE + off, l01, l23);
            split2(fv[u].x, fv[u].y, h01, l01);
            split2(fv[u].z, fv[u].w, h23, l23);
            STS_V2(base + 2 * FA_TILE + off, h01, h23);
            STS_V2(base + 3 * FA_TILE + off, l01, l23);
        }
    };

    fetchKV(0);
    storeKV(0);
    if (ntiles > 1) fetchKV(1);

#pragma unroll 1
    for (int c = 0; c < ntiles; c++) {
        __syncthreads();
        if (c + 1 < ntiles) storeKV((c + 1) & 1);
        if (c + 2 < ntiles) fetchKV(c + 2);

        const int c0 = c * 64;
        if (c0 <= rw + 15) {
            const unsigned kb = sb + (unsigned)(c & 1) * FA_STAGE;

            float s[8][4];
#pragma unroll
            for (int j = 0; j < 8; j++)
#pragma unroll
                for (int r = 0; r < 4; r++) s[j][r] = 0.f;

#pragma unroll
            for (int j = 0; j < 8; j++) {
                const unsigned bd = kb + (8 * j + (lane & 7)) * FA_ROW
                                  + ((lane >> 3) & 1) * 16;
#pragma unroll
                for (int kc = 0; kc < 4; kc++) {
                    unsigned bh0, bh1, bl0, bl1;
                    LDSM_X2(bh0, bh1, bd + kc * 32);
                    LDSM_X2(bl0, bl1, bd + kc * 32 + FA_TILE);
                    MMA_BF16(s[j][0], s[j][1], s[j][2], s[j][3],
                             QH[kc][0], QH[kc][1], QH[kc][2], QH[kc][3], bh0, bh1);
                    MMA_BF16(s[j][0], s[j][1], s[j][2], s[j][3],
                             QH[kc][0], QH[kc][1], QH[kc][2], QH[kc][3], bl0, bl1);
                    MMA_BF16(s[j][0], s[j][1], s[j][2], s[j][3],
                             QL[kc][0], QL[kc][1], QL[kc][2], QL[kc][3], bh0, bh1);
                }
            }

            if (c0 + 63 > rw) {
                const int rA = rw + g;
                const int rB = rw + g + 8;
#pragma unroll
                for (int j = 0; j < 8; j++) {
                    int col = c0 + 8 * j + 2 * t;
                    if (col > rA)     s[j][0] = -1e30f;
                    if (col + 1 > rA) s[j][1] = -1e30f;
                    if (col > rB)     s[j][2] = -1e30f;
                    if (col + 1 > rB) s[j][3] = -1e30f;
                }
            }

            float t0 = -1e30f, t1 = -1e30f;
#pragma unroll
            for (int j = 0; j < 8; j++) {
                t0 = fmaxf(t0, fmaxf(s[j][0], s[j][1]));
                t1 = fmaxf(t1, fmaxf(s[j][2], s[j][3]));
            }
            t0 = fmaxf(t0, __shfl_xor_sync(0xffffffff, t0, 1));
            t0 = fmaxf(t0, __shfl_xor_sync(0xffffffff, t0, 2));
            t1 = fmaxf(t1, __shfl_xor_sync(0xffffffff, t1, 1));
            t1 = fmaxf(t1, __shfl_xor_sync(0xffffffff, t1, 2));
            const float mn0 = fmaxf(m0r, t0);
            const float mn1 = fmaxf(m1r, t1);
            const float sc0 = __expf(m0r - mn0);
            const float sc1 = __expf(m1r - mn1);
            float sum0 = 0.f, sum1 = 0.f;
#pragma unroll
            for (int j = 0; j < 8; j++) {
                float p0 = __expf(s[j][0] - mn0);
                float p1 = __expf(s[j][1] - mn0);
                float p2 = __expf(s[j][2] - mn1);
                float p3 = __expf(s[j][3] - mn1);
                s[j][0] = p0; s[j][1] = p1; s[j][2] = p2; s[j][3] = p3;
                sum0 += p0 + p1;
                sum1 += p2 + p3;
            }
            sum0 += __shfl_xor_sync(0xffffffff, sum0, 1);
            sum0 += __shfl_xor_sync(0xffffffff, sum0, 2);
            sum1 += __shfl_xor_sync(0xffffffff, sum1, 1);
            sum1 += __shfl_xor_sync(0xffffffff, sum1, 2);
            l0 = l0 * sc0 + sum0;
            l1 = l1 * sc1 + sum1;
            m0r = mn0; m1r = mn1;
#pragma unroll
            for (int j = 0; j < 8; j++) {
                o[j][0] *= sc0; o[j][1] *= sc0;
                o[j][2] *= sc1; o[j][3] *= sc1;
            }

#pragma unroll
            for (int kc2 = 0; kc2 < 4; kc2++) {
                unsigned ph[4], pl[4];
                split2(s[2 * kc2][0],     s[2 * kc2][1],     ph[0], pl[0]);
                split2(s[2 * kc2][2],     s[2 * kc2][3],     ph[1], pl[1]);
                split2(s[2 * kc2 + 1][0], s[2 * kc2 + 1][1], ph[2], pl[2]);
                split2(s[2 * kc2 + 1][2], s[2 * kc2 + 1][3], ph[3], pl[3]);
                const unsigned vrow = kb + 2 * FA_TILE
                                    + (16 * kc2 + (lane & 15)) * FA_ROW;
#pragma unroll
                for (int j = 0; j < 8; j++) {
                    unsigned v0, v1, w0, w1;
                    LDSM_X2_T(v0, v1, vrow + j * 16);
                    LDSM_X2_T(w0, w1, vrow + j * 16 + FA_TILE);
                    MMA_BF16(o[j][0], o[j][1], o[j][2], o[j][3],
                             ph[0], ph[1], ph[2], ph[3], v0, v1);
                    MMA_BF16(o[j][0], o[j][1], o[j][2], o[j][3],
                             ph[0], ph[1], ph[2], ph[3], w0, w1);
                    MMA_BF16(o[j][0], o[j][1], o[j][2], o[j][3],
                             pl[0], pl[1], pl[2], pl[3], v0, v1);
                }
            }
        }
    }

    const float inv0 = 1.0f / l0;
    const float inv1 = 1.0f / l1;
    const int rA = rw + g;
    const int rB = rw + g + 8;
#pragma unroll
    for (int j = 0; j < 8; j++) {
        const int col = hb + 8 * j + 2 * t;
        float2 oa, ob;
        oa.x = o[j][0] * inv0; oa.y = o[j][1] * inv0;
        ob.x = o[j][2] * inv1; ob.y = o[j][3] * inv1;
        *(float2*)&O[(size_t)rA * EMB + col] = oa;
        *(float2*)&O[(size_t)rB * EMB + col] = ob;
    }
}

// ---------------------------------------------------------------------------
// Launch
// ---------------------------------------------------------------------------
extern "C" void kernel_launch(void* const* d_in, const int* in_sizes, int n_in,
                              void* d_out, int out_size)
{
    const float* X  = (const float*)d_in[0];
    const float* Wq = (const float*)d_in[1];
    const float* bq = (const float*)d_in[2];
    const float* Wk = (const float*)d_in[3];
    const float* bk = (const float*)d_in[4];
    const float* Wv = (const float*)d_in[5];
    const float* bv = (const float*)d_in[6];
    const float* Wo = (const float*)d_in[7];
    const float* bo = (const float*)d_in[8];
    float* out = (float*)d_out;

    void *pQ, *pK, *pV, *pO;
    cudaGetSymbolAddress(&pQ, g_Q);
    cudaGetSymbolAddress(&pK, g_K);
    cudaGetSymbolAddress(&pV, g_V);
    cudaGetSymbolAddress(&pO, g_O);
    float* Qb = (float*)pQ;
    float* Kb = (float*)pK;
    float* Vb = (float*)pV;
    float* Ob = (float*)pO;

    cudaFuncSetAttribute(gemm_mma_kernel,
                         cudaFuncAttributeMaxDynamicSharedMemorySize, GEMM_SMEM);
    cudaFuncSetAttribute(flash_attn_mma_kernel,
                         cudaFuncAttributeMaxDynamicSharedMemorySize, FA_SMEM);

    dim3 gg(EMB / 128, SEQ / 128);

    // Q projection: bf16x3 mma (verified)
    gemm_mma_kernel<<<gg, 256, GEMM_SMEM>>>(X, Wq, bq, Qb, SCALING);

    // K + V projections with fused quantize, one launch (role = blockIdx.z)
    kv_gemm_quant_kernel<<<dim3(EMB / 128, SEQ / 128, 2), 256>>>(
        X, Wk, bk, Kb, Wv, bv, Vb);

    flash_attn_mma_kernel<<<dim3(SEQ / 128, NHEAD), 256, FA_SMEM>>>(Qb, Kb, Vb, Ob);

    // Output projection: bf16x3 mma (verified)
    gemm_mma_kernel<<<gg, 256, GEMM_SMEM>>>(Ob, Wo, bo, out, 1.0f);
}

// round 15
// speedup vs baseline: 1.0981x; 1.0085x over previous
#include <cuda_runtime.h>
#include <cuda_bf16.h>

#define SEQ 2048
#define EMB 2048
#define NHEAD 32
#define HDIM 64
#define SCALING 0.125f

// Scratch buffers (allocation-free rule: __device__ globals)
__device__ float g_Q[SEQ * EMB];
__device__ float g_K[SEQ * EMB];
__device__ float g_V[SEQ * EMB];
__device__ float g_O[SEQ * EMB];

// ---------------------------------------------------------------------------
// helpers
// ---------------------------------------------------------------------------
__device__ __forceinline__ unsigned s2u(const void* p) {
    unsigned a;
    asm("{ .reg .u64 t; cvta.to.shared.u64 t, %1; cvt.u32.u64 %0, t; }"
        : "=r"(a) : "l"(p));
    return a;
}

// fp32 pair -> packed bf16x2 hi + packed bf16x2 residual (low half = a)
__device__ __forceinline__ void split2(float a, float b, unsigned& hi, unsigned& lo) {
    unsigned h;
    asm("cvt.rn.bf16x2.f32 %0, %1, %2;" : "=r"(h) : "f"(b), "f"(a));
    float ah = __uint_as_float(h << 16);
    float bh = __uint_as_float(h & 0xFFFF0000u);
    float ra = a - ah;
    float rb = b - bh;
    unsigned l;
    asm("cvt.rn.bf16x2.f32 %0, %1, %2;" : "=r"(l) : "f"(rb), "f"(ra));
    hi = h; lo = l;
}

#define MMA_BF16(C0, C1, C2, C3, A0, A1, A2, A3, B0, B1)                      \
    asm volatile(                                                             \
        "mma.sync.aligned.m16n8k16.row.col.f32.bf16.bf16.f32 "                \
        "{%0,%1,%2,%3}, {%4,%5,%6,%7}, {%8,%9}, {%0,%1,%2,%3};"               \
        : "+f"(C0), "+f"(C1), "+f"(C2), "+f"(C3)                              \
        : "r"(A0), "r"(A1), "r"(A2), "r"(A3), "r"(B0), "r"(B1))

#define LDSM_X4(R0, R1, R2, R3, ADDR)                                         \
    asm volatile("ldmatrix.sync.aligned.m8n8.x4.shared.b16 {%0,%1,%2,%3}, [%4];" \
        : "=r"(R0), "=r"(R1), "=r"(R2), "=r"(R3) : "r"(ADDR))

#define LDSM_X2(R0, R1, ADDR)                                                 \
    asm volatile("ldmatrix.sync.aligned.m8n8.x2.shared.b16 {%0,%1}, [%2];"    \
        : "=r"(R0), "=r"(R1) : "r"(ADDR))

#define LDSM_X2_T(R0, R1, ADDR)                                               \
    asm volatile("ldmatrix.sync.aligned.m8n8.x2.trans.shared.b16 {%0,%1}, [%2];" \
        : "=r"(R0), "=r"(R1) : "r"(ADDR))

#define STS_V2(ADDR, V0, V1)                                                  \
    asm volatile("st.shared.v2.b32 [%0], {%1,%2};" :: "r"(ADDR), "r"(V0), "r"(V1) : "memory")

// ---------------------------------------------------------------------------
// bf16x3 GEMM (verified round 11) — Q and output projections.
// ---------------------------------------------------------------------------
#define ROW_B 80
#define TILE_B (128 * ROW_B)
#define STAGE_B (4 * TILE_B)
#define GEMM_SMEM (2 * STAGE_B)         // 81920
#define NCH 64

__global__ __launch_bounds__(256, 1)
void gemm_mma_kernel(const float* __restrict__ A, const float* __restrict__ B,
                     const float* __restrict__ bias, float* __restrict__ C,
                     float scale)
{
    extern __shared__ char smem[];
    const unsigned sb = s2u(smem);
    const int tid = threadIdx.x;
    const int wid = tid >> 5;
    const int lane = tid & 31;
    const int wm = wid & 1;
    const int wn = wid >> 1;
    const int m0 = blockIdx.y * 128;
    const int n0 = blockIdx.x * 128;

    float acc[4][4][4];
#pragma unroll
    for (int i = 0; i < 4; i++)
#pragma unroll
        for (int j = 0; j < 4; j++)
#pragma unroll
            for (int r = 0; r < 4; r++) acc[i][j][r] = 0.f;

    float4 fa[4], fb[4];

    auto fetch = [&](int c) {
        const int k0 = c * 32;
#pragma unroll
        for (int u = 0; u < 4; u++) {
            int slot = tid + u * 256;
            int row = slot >> 3;
            int kq = (slot & 7) << 2;
            fa[u] = *(const float4*)&A[(size_t)(m0 + row) * EMB + k0 + kq];
            fb[u] = *(const float4*)&B[(size_t)(n0 + row) * EMB + k0 + kq];
        }
    };

    auto store_stage = [&](int s) {
        const unsigned base = sb + (unsigned)s * STAGE_B;
#pragma unroll
        for (int u = 0; u < 4; u++) {
            int slot = tid + u * 256;
            int row = slot >> 3;
            int kq = (slot & 7) << 2;
            unsigned off = (unsigned)(row * ROW_B + kq * 2);
            unsigned h01, l01, h23, l23;
            split2(fa[u].x, fa[u].y, h01, l01);
            split2(fa[u].z, fa[u].w, h23, l23);
            STS_V2(base + off, h01, h23);
            STS_V2(base + TILE_B + off, l01, l23);
            split2(fb[u].x, fb[u].y, h01, l01);
            split2(fb[u].z, fb[u].w, h23, l23);
            STS_V2(base + 2 * TILE_B + off, h01, h23);
            STS_V2(base + 3 * TILE_B + off, l01, l23);
        }
    };

    const unsigned a_rl = (unsigned)((lane & 7) + ((lane >> 3) & 1) * 8);
    const unsigned a_by = (unsigned)((lane >> 4) * 16);
    const unsigned b_rl = (unsigned)(lane & 7);
    const unsigned b_by = (unsigned)(((lane >> 3) & 1) * 16);

    fetch(0);
    store_stage(0);
    fetch(1);

#pragma unroll 1
    for (int c = 0; c < NCH; c++) {
        __syncthreads();
        if (c + 1 < NCH) store_stage((c + 1) & 1);
        if (c + 2 < NCH) fetch(c + 2);

        const unsigned abase = sb + (unsigned)(c & 1) * STAGE_B;
        const unsigned bbase = abase + 2 * TILE_B;

#pragma unroll
        for (int k16 = 0; k16 < 32; k16 += 16) {
            unsigned Ah[4][4], Al[4][4], Bh[4][2], Bl[4][2];
#pragma unroll
            for (int mt = 0; mt < 4; mt++) {
                unsigned ad = abase + (wm * 64 + mt * 16 + a_rl) * ROW_B
                            + (k16 * 2 + a_by);
                LDSM_X4(Ah[mt][0], Ah[mt][1], Ah[mt][2], Ah[mt][3], ad);
                LDSM_X4(Al[mt][0], Al[mt][1], Al[mt][2], Al[mt][3], ad + TILE_B);
            }
#pragma unroll
            for (int nt = 0; nt < 4; nt++) {
                unsigned bd = bbase + (wn * 32 + nt * 8 + b_rl) * ROW_B
                            + (k16 * 2 + b_by);
                LDSM_X2(Bh[nt][0], Bh[nt][1], bd);
                LDSM_X2(Bl[nt][0], Bl[nt][1], bd + TILE_B);
            }
#pragma unroll
            for (int mt = 0; mt < 4; mt++)
#pragma unroll
                for (int nt = 0; nt < 4; nt++) {
                    float* cc = acc[mt][nt];
                    MMA_BF16(cc[0], cc[1], cc[2], cc[3],
                             Ah[mt][0], Ah[mt][1], Ah[mt][2], Ah[mt][3],
                             Bh[nt][0], Bh[nt][1]);
                    MMA_BF16(cc[0], cc[1], cc[2], cc[3],
                             Ah[mt][0], Ah[mt][1], Ah[mt][2], Ah[mt][3],
                             Bl[nt][0], Bl[nt][1]);
                    MMA_BF16(cc[0], cc[1], cc[2], cc[3],
                             Al[mt][0], Al[mt][1], Al[mt][2], Al[mt][3],
                             Bh[nt][0], Bh[nt][1]);
                }
        }
    }

    const int g = lane >> 2;
    const int c2 = (lane & 3) * 2;
#pragma unroll
    for (int mt = 0; mt < 4; mt++) {
        const int r0 = m0 + wm * 64 + mt * 16 + g;
#pragma unroll
        for (int nt = 0; nt < 4; nt++) {
            const int col = n0 + wn * 32 + nt * 8 + c2;
            float2 bv = *(const float2*)&bias[col];
            float2 o0, o1;
            o0.x = (acc[mt][nt][0] + bv.x) * scale;
            o0.y = (acc[mt][nt][1] + bv.y) * scale;
            o1.x = (acc[mt][nt][2] + bv.x) * scale;
            o1.y = (acc[mt][nt][3] + bv.y) * scale;
            *(float2*)&C[(size_t)r0 * EMB + col] = o0;
            *(float2*)&C[(size_t)(r0 + 8) * EMB + col] = o1;
        }
    }
}

// ---------------------------------------------------------------------------
// QuotRem quantize over a 16-group held by two adjacent threads (8 vals each).
// VERIFIED bitwise-identical to the standalone kernel.
// ---------------------------------------------------------------------------
__device__ __forceinline__ void quant16_pair(float v[8]) {
    float mx = v[0], mn = v[0];
#pragma unroll
    for (int i = 1; i < 8; i++) {
        mx = fmaxf(mx, v[i]);
        mn = fminf(mn, v[i]);
    }
    mx = fmaxf(mx, __shfl_xor_sync(0xffffffff, mx, 1));
    mn = fminf(mn, __shfl_xor_sync(0xffffffff, mn, 1));
    float ma = fmaxf(fmaxf(mx, -mn), 1e-8f);

    float l2 = log2f(ma);
    float bflo = exp2f(floorf(l2));
    float bcei = exp2f(ceilf(l2));
    float base = (fabsf(ma - bflo) <= fabsf(bcei - ma)) ? bflo : bcei;
    base = fminf(fmaxf(base, 1.0f), 128.0f);

    float sign = (fabsf(mx) >= fabsf(mn)) ? 1.0f : -1.0f;
    float hb = 0.5f * base;
    float sb = sign * base;

    float qs[8], r[8];
    float mar = 0.f;
#pragma unroll
    for (int i = 0; i < 8; i++) {
        float q = (v[i] * sign >= hb) ? 1.0f : 0.0f;
        qs[i] = q * sb;
        r[i] = v[i] - qs[i];
        mar = fmaxf(mar, fabsf(r[i]));
    }
    mar = fmaxf(mar, __shfl_xor_sync(0xffffffff, mar, 1));
    mar = fmaxf(mar, 1e-8f);
    float sr = mar * (1.0f / 3.0f);

#pragma unroll
    for (int i = 0; i < 8; i++) {
        float rq = rintf(r[i] / sr);
        rq = fminf(fmaxf(rq, -4.0f), 3.0f);
        v[i] = qs[i] + rq * sr;
    }
}

// ---------------------------------------------------------------------------
// fp32 SIMT GEMM + fused QuotRem quantize — K and V in ONE launch
// (blockIdx.z selects role). Sequential fp32 FFMA is quantizer-pinned.
// ---------------------------------------------------------------------------
#define BM 128
#define BN 128
#define BK 16
#define GK 2048

__global__ __launch_bounds__(256)
void kv_gemm_quant_kernel(
    const float* __restrict__ X,
    const float* __restrict__ Wk, const float* __restrict__ bk, float* __restrict__ Ko,
    const float* __restrict__ Wv, const float* __restrict__ bv, float* __restrict__ Vo)
{
    __shared__ float As[BK][BM];
    __shared__ float Bs[BK][BN];

    const float* B   = (blockIdx.z == 0) ? Wk : Wv;
    const float* bias = (blockIdx.z == 0) ? bk : bv;
    float* C          = (blockIdx.z == 0) ? Ko : Vo;

    const int tid = threadIdx.x;
    const int tx = tid & 15;
    const int ty = tid >> 4;
    const int m0 = blockIdx.y * BM;
    const int n0 = blockIdx.x * BN;

    float acc[8][8];
#pragma unroll
    for (int i = 0; i < 8; i++)
#pragma unroll
        for (int j = 0; j < 8; j++) acc[i][j] = 0.f;

    for (int kt = 0; kt < GK; kt += BK) {
#pragma unroll
        for (int u = 0; u < 2; u++) {
            int i = tid + u * 256;
            int row = i >> 2;
            int kq = (i & 3) << 2;
            float4 a = *(const float4*)&X[(size_t)(m0 + row) * GK + kt + kq];
            As[kq + 0][row] = a.x; As[kq + 1][row] = a.y;
            As[kq + 2][row] = a.z; As[kq + 3][row] = a.w;
            float4 b = *(const float4*)&B[(size_t)(n0 + row) * GK + kt + kq];
            Bs[kq + 0][row] = b.x; Bs[kq + 1][row] = b.y;
            Bs[kq + 2][row] = b.z; Bs[kq + 3][row] = b.w;
        }
        __syncthreads();

#pragma unroll
        for (int k = 0; k < BK; k++) {
            float4 a0 = *(const float4*)&As[k][ty * 8];
            float4 a1 = *(const float4*)&As[k][ty * 8 + 4];
            float4 b0 = *(const float4*)&Bs[k][tx * 8];
            float4 b1 = *(const float4*)&Bs[k][tx * 8 + 4];
            float ar[8] = {a0.x, a0.y, a0.z, a0.w, a1.x, a1.y, a1.z, a1.w};
            float br[8] = {b0.x, b0.y, b0.z, b0.w, b1.x, b1.y, b1.z, b1.w};
#pragma unroll
            for (int i = 0; i < 8; i++)
#pragma unroll
                for (int j = 0; j < 8; j++)
                    acc[i][j] += ar[i] * br[j];
        }
        __syncthreads();
    }

    float4 bv0 = *(const float4*)&bias[n0 + tx * 8];
    float4 bv1 = *(const float4*)&bias[n0 + tx * 8 + 4];
    float bb[8] = {bv0.x, bv0.y, bv0.z, bv0.w, bv1.x, bv1.y, bv1.z, bv1.w};

#pragma unroll
    for (int i = 0; i < 8; i++) {
        int row = m0 + ty * 8 + i;
        float v[8];
#pragma unroll
        for (int j = 0; j < 8; j++) v[j] = acc[i][j] + bb[j];
        quant16_pair(v);                   // fused QuotRem quantize (verified)
        float4 o0, o1;
        o0.x = v[0]; o0.y = v[1]; o0.z = v[2]; o0.w = v[3];
        o1.x = v[4]; o1.y = v[5]; o1.z = v[6]; o1.w = v[7];
        *(float4*)&C[(size_t)row * GK + n0 + tx * 8] = o0;
        *(float4*)&C[(size_t)row * GK + n0 + tx * 8 + 4] = o1;
    }
}

// ---------------------------------------------------------------------------
// MMA causal flash attention (verified round 7)
// ---------------------------------------------------------------------------
#define FA_ROW 144
#define FA_TILE (64 * FA_ROW)
#define FA_STAGE (4 * FA_TILE)
#define FA_SMEM (2 * FA_STAGE)

__global__ __launch_bounds__(256, 1)
void flash_attn_mma_kernel(const float* __restrict__ Q, const float* __restrict__ K,
                           const float* __restrict__ V, float* __restrict__ O)
{
    extern __shared__ char smem[];
    const unsigned sb = s2u(smem);
    const int tid = threadIdx.x;
    const int wid = tid >> 5;
    const int lane = tid & 31;
    const int head = blockIdx.y;
    const int bx = (int)gridDim.x - 1 - (int)blockIdx.x;
    const int r0 = bx * 128;
    const int hb = head * HDIM;
    const int rw = r0 + wid * 16;
    const int g = lane >> 2;
    const int t = lane & 3;

#pragma unroll
    for (int u = 0; u < 8; u++) {
        int slot = tid + u * 256;
        int row = slot >> 4;
        int dq = (slot & 15) << 2;
        float4 v = *(const float4*)&Q[(size_t)(r0 + row) * EMB + hb + dq];
        unsigned h01, l01, h23, l23;
        split2(v.x, v.y, h01, l01);
        split2(v.z, v.w, h23, l23);
        unsigned off = (unsigned)(row * FA_ROW + dq * 2);
        STS_V2(sb + off, h01, h23);
        STS_V2(sb + 18432u + off, l01, l23);
    }
    __syncthreads();

    const unsigned a_rl = (unsigned)((lane & 7) + ((lane >> 3) & 1) * 8);
    const unsigned a_by = (unsigned)((lane >> 4) * 16);
    unsigned QH[4][4], QL[4][4];
#pragma unroll
    for (int kc = 0; kc < 4; kc++) {
        unsigned ad = sb + (wid * 16 + a_rl) * FA_ROW + kc * 32 + a_by;
        LDSM_X4(QH[kc][0], QH[kc][1], QH[kc][2], QH[kc][3], ad);
        LDSM_X4(QL[kc][0], QL[kc][1], QL[kc][2], QL[kc][3], ad + 18432u);
    }
    __syncthreads();

    float o[8][4];
#pragma unroll
    for (int j = 0; j < 8; j++)
#pragma unroll
        for (int r = 0; r < 4; r++) o[j][r] = 0.f;
    float m0r = -1e30f, m1r = -1e30f, l0 = 0.f, l1 = 0.f;

    const int ntiles = 2 * bx + 2;
    float4 fk[4], fv[4];

    auto fetchKV = [&](int tI) {
        const int c0 = tI * 64;
#pragma unroll
        for (int u = 0; u < 4; u++) {
            int slot = tid + u * 256;
            int kr = slot >> 4;
            int dq = (slot & 15) << 2;
            fk[u] = *(const float4*)&K[(size_t)(c0 + kr) * EMB + hb + dq];
            fv[u] = *(const float4*)&V[(size_t)(c0 + kr) * EMB + hb + dq];
        }
    };
    auto storeKV = [&](int s) {
        const unsigned base = sb + (unsigned)s * FA_STAGE;
#pragma unroll
        for (int u = 0; u < 4; u++) {
            int slot = tid + u * 256;
            int kr = slot >> 4;
            int dq = (slot & 15) << 2;
            unsigned off = (unsigned)(kr * FA_ROW + dq * 2);
            unsigned h01, l01, h23, l23;
            split2(fk[u].x, fk[u].y, h01, l01);
            split2(fk[u].z, fk[u].w, h23, l23);
            STS_V2(base + off, h01, h23);
            STS_V2(base + FA_TILE + off, l01, l23);
            split2(fv[u].x, fv[u].y, h01, l01);
            split2(fv[u].z, fv[u].w, h23, l23);
            STS_V2(base + 2 * FA_TILE + off, h01, h23);
            STS_V2(base + 3 * FA_TILE + off, l01, l23);
        }
    };

    fetchKV(0);
    storeKV(0);
    if (ntiles > 1) fetchKV(1);

#pragma unroll 1
    for (int c = 0; c < ntiles; c++) {
        __syncthreads();
        if (c + 1 < ntiles) storeKV((c + 1) & 1);
        if (c + 2 < ntiles) fetchKV(c + 2);

        const int c0 = c * 64;
        if (c0 <= rw + 15) {
            const unsigned kb = sb + (unsigned)(c & 1) * FA_STAGE;

            float s[8][4];
#pragma unroll
            for (int j = 0; j < 8; j++)
#pragma unroll
                for (int r = 0; r < 4; r++) s[j][r] = 0.f;

#pragma unroll
            for (int j = 0; j < 8; j++) {
                const unsigned bd = kb + (8 * j + (lane & 7)) * FA_ROW
                                  + ((lane >> 3) & 1) * 16;
#pragma unroll
                for (int kc = 0; kc < 4; kc++) {
                    unsigned bh0, bh1, bl0, bl1;
                    LDSM_X2(bh0, bh1, bd + kc * 32);
                    LDSM_X2(bl0, bl1, bd + kc * 32 + FA_TILE);
                    MMA_BF16(s[j][0], s[j][1], s[j][2], s[j][3],
                             QH[kc][0], QH[kc][1], QH[kc][2], QH[kc][3], bh0, bh1);
                    MMA_BF16(s[j][0], s[j][1], s[j][2], s[j][3],
                             QH[kc][0], QH[kc][1], QH[kc][2], QH[kc][3], bl0, bl1);
                    MMA_BF16(s[j][0], s[j][1], s[j][2], s[j][3],
                             QL[kc][0], QL[kc][1], QL[kc][2], QL[kc][3], bh0, bh1);
                }
            }

            if (c0 + 63 > rw) {
                const int rA = rw + g;
                const int rB = rw + g + 8;
#pragma unroll
                for (int j = 0; j < 8; j++) {
                    int col = c0 + 8 * j + 2 * t;
                    if (col > rA)     s[j][0] = -1e30f;
                    if (col + 1 > rA) s[j][1] = -1e30f;
                    if (col > rB)     s[j][2] = -1e30f;
                    if (col + 1 > rB) s[j][3] = -1e30f;
                }
            }

            float t0 = -1e30f, t1 = -1e30f;
#pragma unroll
            for (int j = 0; j < 8; j++) {
                t0 = fmaxf(t0, fmaxf(s[j][0], s[j][1]));
                t1 = fmaxf(t1, fmaxf(s[j][2], s[j][3]));
            }
            t0 = fmaxf(t0, __shfl_xor_sync(0xffffffff, t0, 1));
            t0 = fmaxf(t0, __shfl_xor_sync(0xffffffff, t0, 2));
            t1 = fmaxf(t1, __shfl_xor_sync(0xffffffff, t1, 1));
            t1 = fmaxf(t1, __shfl_xor_sync(0xffffffff, t1, 2));
            const float mn0 = fmaxf(m0r, t0);
            const float mn1 = fmaxf(m1r, t1);
            const float sc0 = __expf(m0r - mn0);
            const float sc1 = __expf(m1r - mn1);
            float sum0 = 0.f, sum1 = 0.f;
#pragma unroll
            for (int j = 0; j < 8; j++) {
                float p0 = __expf(s[j][0] - mn0);
                float p1 = __expf(s[j][1] - mn0);
                float p2 = __expf(s[j][2] - mn1);
                float p3 = __expf(s[j][3] - mn1);
                s[j][0] = p0; s[j][1] = p1; s[j][2] = p2; s[j][3] = p3;
                sum0 += p0 + p1;
                sum1 += p2 + p3;
            }
            sum0 += __shfl_xor_sync(0xffffffff, sum0, 1);
            sum0 += __shfl_xor_sync(0xffffffff, sum0, 2);
            sum1 += __shfl_xor_sync(0xffffffff, sum1, 1);
            sum1 += __shfl_xor_sync(0xffffffff, sum1, 2);
            l0 = l0 * sc0 + sum0;
            l1 = l1 * sc1 + sum1;
            m0r = mn0; m1r = mn1;
#pragma unroll
            for (int j = 0; j < 8; j++) {
                o[j][0] *= sc0; o[j][1] *= sc0;
                o[j][2] *= sc1; o[j][3] *= sc1;
            }

#pragma unroll
            for (int kc2 = 0; kc2 < 4; kc2++) {
                unsigned ph[4], pl[4];
                split2(s[2 * kc2][0],     s[2 * kc2][1],     ph[0], pl[0]);
                split2(s[2 * kc2][2],     s[2 * kc2][3],     ph[1], pl[1]);
                split2(s[2 * kc2 + 1][0], s[2 * kc2 + 1][1], ph[2], pl[2]);
                split2(s[2 * kc2 + 1][2], s[2 * kc2 + 1][3], ph[3], pl[3]);
                const unsigned vrow = kb + 2 * FA_TILE
                                    + (16 * kc2 + (lane & 15)) * FA_ROW;
#pragma unroll
                for (int j = 0; j < 8; j++) {
                    unsigned v0, v1, w0, w1;
                    LDSM_X2_T(v0, v1, vrow + j * 16);
                    LDSM_X2_T(w0, w1, vrow + j * 16 + FA_TILE);
                    MMA_BF16(o[j][0], o[j][1], o[j][2], o[j][3],
                             ph[0], ph[1], ph[2], ph[3], v0, v1);
                    MMA_BF16(o[j][0], o[j][1], o[j][2], o[j][3],
                             ph[0], ph[1], ph[2], ph[3], w0, w1);
                    MMA_BF16(o[j][0], o[j][1], o[j][2], o[j][3],
                             pl[0], pl[1], pl[2], pl[3], v0, v1);
                }
            }
        }
    }

    const float inv0 = 1.0f / l0;
    const float inv1 = 1.0f / l1;
    const int rA = rw + g;
    const int rB = rw + g + 8;
#pragma unroll
    for (int j = 0; j < 8; j++) {
        const int col = hb + 8 * j + 2 * t;
        float2 oa, ob;
        oa.x = o[j][0] * inv0; oa.y = o[j][1] * inv0;
        ob.x = o[j][2] * inv1; ob.y = o[j][3] * inv1;
        *(float2*)&O[(size_t)rA * EMB + col] = oa;
        *(float2*)&O[(size_t)rB * EMB + col] = ob;
    }
}

// ---------------------------------------------------------------------------
// Launch — fork/join: Q-proj (tensor-bound) runs on a side stream
// concurrently with the KV SIMT kernel (FMA-bound). Event-based capture
// fork/join is graph-capturable; no syncs, no device allocations.
// ---------------------------------------------------------------------------
extern "C" void kernel_launch(void* const* d_in, const int* in_sizes, int n_in,
                              void* d_out, int out_size)
{
    const float* X  = (const float*)d_in[0];
    const float* Wq = (const float*)d_in[1];
    const float* bq = (const float*)d_in[2];
    const float* Wk = (const float*)d_in[3];
    const float* bk = (const float*)d_in[4];
    const float* Wv = (const float*)d_in[5];
    const float* bv = (const float*)d_in[6];
    const float* Wo = (const float*)d_in[7];
    const float* bo = (const float*)d_in[8];
    float* out = (float*)d_out;

    void *pQ, *pK, *pV, *pO;
    cudaGetSymbolAddress(&pQ, g_Q);
    cudaGetSymbolAddress(&pK, g_K);
    cudaGetSymbolAddress(&pV, g_V);
    cudaGetSymbolAddress(&pO, g_O);
    float* Qb = (float*)pQ;
    float* Kb = (float*)pK;
    float* Vb = (float*)pV;
    float* Ob = (float*)pO;

    cudaFuncSetAttribute(gemm_mma_kernel,
                         cudaFuncAttributeMaxDynamicSharedMemorySize, GEMM_SMEM);
    cudaFuncSetAttribute(flash_attn_mma_kernel,
                         cudaFuncAttributeMaxDynamicSharedMemorySize, FA_SMEM);

    dim3 gg(EMB / 128, SEQ / 128);

    // side stream + fork/join events (host objects; created per call)
    cudaStream_t side;
    cudaStreamCreateWithFlags(&side, cudaStreamNonBlocking);
    cudaEvent_t evFork, evJoin;
    cudaEventCreateWithFlags(&evFork, cudaEventDisableTiming);
    cudaEventCreateWithFlags(&evJoin, cudaEventDisableTiming);

    // fork: side stream joins the capture graph
    cudaEventRecord(evFork, 0);
    cudaStreamWaitEvent(side, evFork, 0);

    // Q projection on side stream (tensor pipe) — overlaps KV (FMA pipe)
    gemm_mma_kernel<<<gg, 256, GEMM_SMEM, side>>>(X, Wq, bq, Qb, SCALING);

    // K + V projections with fused quantize on main stream
    kv_gemm_quant_kernel<<<dim3(EMB / 128, SEQ / 128, 2), 256>>>(
        X, Wk, bk, Kb, Wv, bv, Vb);

    // join: main stream waits for Q before attention
    cudaEventRecord(evJoin, side);
    cudaStreamWaitEvent(0, evJoin, 0);

    flash_attn_mma_kernel<<<dim3(SEQ / 128, NHEAD), 256, FA_SMEM>>>(Qb, Kb, Vb, Ob);

    // Output projection: bf16x3 mma (verified)
    gemm_mma_kernel<<<gg, 256, GEMM_SMEM>>>(Ob, Wo, bo, out, 1.0f);

    // release host-side handles (safe during capture; resources freed lazily)
    cudaEventDestroy(evFork);
    cudaEventDestroy(evJoin);
    cudaStreamDestroy(side);
}

// round 16
// speedup vs baseline: 1.1019x; 1.0035x over previous
#include <cuda_runtime.h>
#include <cuda_bf16.h>

#define SEQ 2048
#define EMB 2048
#define NHEAD 32
#define HDIM 64
#define SCALING 0.125f

// Scratch buffers (allocation-free rule: __device__ globals)
__device__ float g_Q[SEQ * EMB];
__device__ float g_K[SEQ * EMB];
__device__ float g_V[SEQ * EMB];
__device__ float g_O[SEQ * EMB];

// ---------------------------------------------------------------------------
// helpers
// ---------------------------------------------------------------------------
__device__ __forceinline__ unsigned s2u(const void* p) {
    unsigned a;
    asm("{ .reg .u64 t; cvta.to.shared.u64 t, %1; cvt.u32.u64 %0, t; }"
        : "=r"(a) : "l"(p));
    return a;
}

// fp32 pair -> packed bf16x2 hi + packed bf16x2 residual (low half = a)
__device__ __forceinline__ void split2(float a, float b, unsigned& hi, unsigned& lo) {
    unsigned h;
    asm("cvt.rn.bf16x2.f32 %0, %1, %2;" : "=r"(h) : "f"(b), "f"(a));
    float ah = __uint_as_float(h << 16);
    float bh = __uint_as_float(h & 0xFFFF0000u);
    float ra = a - ah;
    float rb = b - bh;
    unsigned l;
    asm("cvt.rn.bf16x2.f32 %0, %1, %2;" : "=r"(l) : "f"(rb), "f"(ra));
    hi = h; lo = l;
}

#define MMA_BF16(C0, C1, C2, C3, A0, A1, A2, A3, B0, B1)                      \
    asm volatile(                                                             \
        "mma.sync.aligned.m16n8k16.row.col.f32.bf16.bf16.f32 "                \
        "{%0,%1,%2,%3}, {%4,%5,%6,%7}, {%8,%9}, {%0,%1,%2,%3};"               \
        : "+f"(C0), "+f"(C1), "+f"(C2), "+f"(C3)                              \
        : "r"(A0), "r"(A1), "r"(A2), "r"(A3), "r"(B0), "r"(B1))

#define LDSM_X4(R0, R1, R2, R3, ADDR)                                         \
    asm volatile("ldmatrix.sync.aligned.m8n8.x4.shared.b16 {%0,%1,%2,%3}, [%4];" \
        : "=r"(R0), "=r"(R1), "=r"(R2), "=r"(R3) : "r"(ADDR))

#define LDSM_X2(R0, R1, ADDR)                                                 \
    asm volatile("ldmatrix.sync.aligned.m8n8.x2.shared.b16 {%0,%1}, [%2];"    \
        : "=r"(R0), "=r"(R1) : "r"(ADDR))

#define LDSM_X2_T(R0, R1, ADDR)                                               \
    asm volatile("ldmatrix.sync.aligned.m8n8.x2.trans.shared.b16 {%0,%1}, [%2];" \
        : "=r"(R0), "=r"(R1) : "r"(ADDR))

#define STS_V2(ADDR, V0, V1)                                                  \
    asm volatile("st.shared.v2.b32 [%0], {%1,%2};" :: "r"(ADDR), "r"(V0), "r"(V1) : "memory")

// ---------------------------------------------------------------------------
// bf16x3 GEMM — Q and output projections. Re-tiled for occupancy 2:
// CTA tile 128x64, 8 warps (4m x 2n), warp tile 32x32, acc = 32 regs.
// Per-element accumulation sequence is IDENTICAL to the verified 128x128
// version (same c-chunk order, k16 order, 3-term order) -> bitwise-equal C.
// SMEM stage = Ah(128x80) | Al | Bh(64x80) | Bl, x2 stages = 61440 B.
// ---------------------------------------------------------------------------
#define ROW_B 80
#define A_TILE_B (128 * ROW_B)          // 10240
#define B_TILE_B (64 * ROW_B)           // 5120
#define STAGE_B (2 * A_TILE_B + 2 * B_TILE_B)  // 30720
#define GEMM_SMEM (2 * STAGE_B)         // 61440
#define NCH 64

__global__ __launch_bounds__(256, 2)
void gemm_mma_kernel(const float* __restrict__ A, const float* __restrict__ B,
                     const float* __restrict__ bias, float* __restrict__ C,
                     float scale)
{
    extern __shared__ char smem[];
    const unsigned sb = s2u(smem);
    const int tid = threadIdx.x;
    const int wid = tid >> 5;
    const int lane = tid & 31;
    const int wm = wid & 3;             // 0..3 (32-row strip)
    const int wn = wid >> 2;            // 0..1 (32-col strip)
    const int m0 = blockIdx.y * 128;
    const int n0 = blockIdx.x * 64;

    float acc[2][4][4];
#pragma unroll
    for (int i = 0; i < 2; i++)
#pragma unroll
        for (int j = 0; j < 4; j++)
#pragma unroll
            for (int r = 0; r < 4; r++) acc[i][j][r] = 0.f;

    float4 fa[4], fb[2];

    auto fetch = [&](int c) {
        const int k0 = c * 32;
#pragma unroll
        for (int u = 0; u < 4; u++) {
            int slot = tid + u * 256;       // 0..1023
            int row = slot >> 3;            // 0..127
            int kq = (slot & 7) << 2;
            fa[u] = *(const float4*)&A[(size_t)(m0 + row) * EMB + k0 + kq];
        }
#pragma unroll
        for (int u = 0; u < 2; u++) {
            int slot = tid + u * 256;       // 0..511
            int row = slot >> 3;            // 0..63
            int kq = (slot & 7) << 2;
            fb[u] = *(const float4*)&B[(size_t)(n0 + row) * EMB + k0 + kq];
        }
    };

    auto store_stage = [&](int s) {
        const unsigned base = sb + (unsigned)s * STAGE_B;
#pragma unroll
        for (int u = 0; u < 4; u++) {
            int slot = tid + u * 256;
            int row = slot >> 3;
            int kq = (slot & 7) << 2;
            unsigned off = (unsigned)(row * ROW_B + kq * 2);
            unsigned h01, l01, h23, l23;
            split2(fa[u].x, fa[u].y, h01, l01);
            split2(fa[u].z, fa[u].w, h23, l23);
            STS_V2(base + off, h01, h23);
            STS_V2(base + A_TILE_B + off, l01, l23);
        }
#pragma unroll
        for (int u = 0; u < 2; u++) {
            int slot = tid + u * 256;
            int row = slot >> 3;
            int kq = (slot & 7) << 2;
            unsigned off = (unsigned)(row * ROW_B + kq * 2);
            unsigned h01, l01, h23, l23;
            split2(fb[u].x, fb[u].y, h01, l01);
            split2(fb[u].z, fb[u].w, h23, l23);
            STS_V2(base + 2 * A_TILE_B + off, h01, h23);
            STS_V2(base + 2 * A_TILE_B + B_TILE_B + off, l01, l23);
        }
    };

    const unsigned a_rl = (unsigned)((lane & 7) + ((lane >> 3) & 1) * 8);
    const unsigned a_by = (unsigned)((lane >> 4) * 16);
    const unsigned b_rl = (unsigned)(lane & 7);
    const unsigned b_by = (unsigned)(((lane >> 3) & 1) * 16);

    fetch(0);
    store_stage(0);
    fetch(1);

#pragma unroll 1
    for (int c = 0; c < NCH; c++) {
        __syncthreads();
        if (c + 1 < NCH) store_stage((c + 1) & 1);
        if (c + 2 < NCH) fetch(c + 2);

        const unsigned abase = sb + (unsigned)(c & 1) * STAGE_B;
        const unsigned bbase = abase + 2 * A_TILE_B;

#pragma unroll
        for (int k16 = 0; k16 < 32; k16 += 16) {
            unsigned Ah[2][4], Al[2][4], Bh[4][2], Bl[4][2];
#pragma unroll
            for (int mt = 0; mt < 2; mt++) {
                unsigned ad = abase + (wm * 32 + mt * 16 + a_rl) * ROW_B
                            + (k16 * 2 + a_by);
                LDSM_X4(Ah[mt][0], Ah[mt][1], Ah[mt][2], Ah[mt][3], ad);
                LDSM_X4(Al[mt][0], Al[mt][1], Al[mt][2], Al[mt][3], ad + A_TILE_B);
            }
#pragma unroll
            for (int nt = 0; nt < 4; nt++) {
                unsigned bd = bbase + (wn * 32 + nt * 8 + b_rl) * ROW_B
                            + (k16 * 2 + b_by);
                LDSM_X2(Bh[nt][0], Bh[nt][1], bd);
                LDSM_X2(Bl[nt][0], Bl[nt][1], bd + B_TILE_B);
            }
#pragma unroll
            for (int mt = 0; mt < 2; mt++)
#pragma unroll
                for (int nt = 0; nt < 4; nt++) {
                    float* cc = acc[mt][nt];
                    MMA_BF16(cc[0], cc[1], cc[2], cc[3],
                             Ah[mt][0], Ah[mt][1], Ah[mt][2], Ah[mt][3],
                             Bh[nt][0], Bh[nt][1]);
                    MMA_BF16(cc[0], cc[1], cc[2], cc[3],
                             Ah[mt][0], Ah[mt][1], Ah[mt][2], Ah[mt][3],
                             Bl[nt][0], Bl[nt][1]);
                    MMA_BF16(cc[0], cc[1], cc[2], cc[3],
                             Al[mt][0], Al[mt][1], Al[mt][2], Al[mt][3],
                             Bh[nt][0], Bh[nt][1]);
                }
        }
    }

    const int g = lane >> 2;
    const int c2 = (lane & 3) * 2;
#pragma unroll
    for (int mt = 0; mt < 2; mt++) {
        const int r0 = m0 + wm * 32 + mt * 16 + g;
#pragma unroll
        for (int nt = 0; nt < 4; nt++) {
            const int col = n0 + wn * 32 + nt * 8 + c2;
            float2 bv = *(const float2*)&bias[col];
            float2 o0, o1;
            o0.x = (acc[mt][nt][0] + bv.x) * scale;
            o0.y = (acc[mt][nt][1] + bv.y) * scale;
            o1.x = (acc[mt][nt][2] + bv.x) * scale;
            o1.y = (acc[mt][nt][3] + bv.y) * scale;
            *(float2*)&C[(size_t)r0 * EMB + col] = o0;
            *(float2*)&C[(size_t)(r0 + 8) * EMB + col] = o1;
        }
    }
}

// ---------------------------------------------------------------------------
// QuotRem quantize over a 16-group held by two adjacent threads (8 vals each).
// VERIFIED bitwise-identical to the standalone kernel.
// ---------------------------------------------------------------------------
__device__ __forceinline__ void quant16_pair(float v[8]) {
    float mx = v[0], mn = v[0];
#pragma unroll
    for (int i = 1; i < 8; i++) {
        mx = fmaxf(mx, v[i]);
        mn = fminf(mn, v[i]);
    }
    mx = fmaxf(mx, __shfl_xor_sync(0xffffffff, mx, 1));
    mn = fminf(mn, __shfl_xor_sync(0xffffffff, mn, 1));
    float ma = fmaxf(fmaxf(mx, -mn), 1e-8f);

    float l2 = log2f(ma);
    float bflo = exp2f(floorf(l2));
    float bcei = exp2f(ceilf(l2));
    float base = (fabsf(ma - bflo) <= fabsf(bcei - ma)) ? bflo : bcei;
    base = fminf(fmaxf(base, 1.0f), 128.0f);

    float sign = (fabsf(mx) >= fabsf(mn)) ? 1.0f : -1.0f;
    float hb = 0.5f * base;
    float sb = sign * base;

    float qs[8], r[8];
    float mar = 0.f;
#pragma unroll
    for (int i = 0; i < 8; i++) {
        float q = (v[i] * sign >= hb) ? 1.0f : 0.0f;
        qs[i] = q * sb;
        r[i] = v[i] - qs[i];
        mar = fmaxf(mar, fabsf(r[i]));
    }
    mar = fmaxf(mar, __shfl_xor_sync(0xffffffff, mar, 1));
    mar = fmaxf(mar, 1e-8f);
    float sr = mar * (1.0f / 3.0f);

#pragma unroll
    for (int i = 0; i < 8; i++) {
        float rq = rintf(r[i] / sr);
        rq = fminf(fmaxf(rq, -4.0f), 3.0f);
        v[i] = qs[i] + rq * sr;
    }
}

// ---------------------------------------------------------------------------
// fp32 SIMT GEMM + fused QuotRem quantize — K and V in ONE launch
// (blockIdx.z selects role). Sequential fp32 FFMA is quantizer-pinned.
// ---------------------------------------------------------------------------
#define BM 128
#define BN 128
#define BK 16
#define GK 2048

__global__ __launch_bounds__(256)
void kv_gemm_quant_kernel(
    const float* __restrict__ X,
    const float* __restrict__ Wk, const float* __restrict__ bk, float* __restrict__ Ko,
    const float* __restrict__ Wv, const float* __restrict__ bv, float* __restrict__ Vo)
{
    __shared__ float As[BK][BM];
    __shared__ float Bs[BK][BN];

    const float* B   = (blockIdx.z == 0) ? Wk : Wv;
    const float* bias = (blockIdx.z == 0) ? bk : bv;
    float* C          = (blockIdx.z == 0) ? Ko : Vo;

    const int tid = threadIdx.x;
    const int tx = tid & 15;
    const int ty = tid >> 4;
    const int m0 = blockIdx.y * BM;
    const int n0 = blockIdx.x * BN;

    float acc[8][8];
#pragma unroll
    for (int i = 0; i < 8; i++)
#pragma unroll
        for (int j = 0; j < 8; j++) acc[i][j] = 0.f;

    for (int kt = 0; kt < GK; kt += BK) {
#pragma unroll
        for (int u = 0; u < 2; u++) {
            int i = tid + u * 256;
            int row = i >> 2;
            int kq = (i & 3) << 2;
            float4 a = *(const float4*)&X[(size_t)(m0 + row) * GK + kt + kq];
            As[kq + 0][row] = a.x; As[kq + 1][row] = a.y;
            As[kq + 2][row] = a.z; As[kq + 3][row] = a.w;
            float4 b = *(const float4*)&B[(size_t)(n0 + row) * GK + kt + kq];
            Bs[kq + 0][row] = b.x; Bs[kq + 1][row] = b.y;
            Bs[kq + 2][row] = b.z; Bs[kq + 3][row] = b.w;
        }
        __syncthreads();

#pragma unroll
        for (int k = 0; k < BK; k++) {
            float4 a0 = *(const float4*)&As[k][ty * 8];
            float4 a1 = *(const float4*)&As[k][ty * 8 + 4];
            float4 b0 = *(const float4*)&Bs[k][tx * 8];
            float4 b1 = *(const float4*)&Bs[k][tx * 8 + 4];
            float ar[8] = {a0.x, a0.y, a0.z, a0.w, a1.x, a1.y, a1.z, a1.w};
            float br[8] = {b0.x, b0.y, b0.z, b0.w, b1.x, b1.y, b1.z, b1.w};
#pragma unroll
            for (int i = 0; i < 8; i++)
#pragma unroll
                for (int j = 0; j < 8; j++)
                    acc[i][j] += ar[i] * br[j];
        }
        __syncthreads();
    }

    float4 bv0 = *(const float4*)&bias[n0 + tx * 8];
    float4 bv1 = *(const float4*)&bias[n0 + tx * 8 + 4];
    float bb[8] = {bv0.x, bv0.y, bv0.z, bv0.w, bv1.x, bv1.y, bv1.z, bv1.w};

#pragma unroll
    for (int i = 0; i < 8; i++) {
        int row = m0 + ty * 8 + i;
        float v[8];
#pragma unroll
        for (int j = 0; j < 8; j++) v[j] = acc[i][j] + bb[j];
        quant16_pair(v);                   // fused QuotRem quantize (verified)
        float4 o0, o1;
        o0.x = v[0]; o0.y = v[1]; o0.z = v[2]; o0.w = v[3];
        o1.x = v[4]; o1.y = v[5]; o1.z = v[6]; o1.w = v[7];
        *(float4*)&C[(size_t)row * GK + n0 + tx * 8] = o0;
        *(float4*)&C[(size_t)row * GK + n0 + tx * 8 + 4] = o1;
    }
}

// ---------------------------------------------------------------------------
// MMA causal flash attention (verified round 7)
// ---------------------------------------------------------------------------
#define FA_ROW 144
#define FA_TILE (64 * FA_ROW)
#define FA_STAGE (4 * FA_TILE)
#define FA_SMEM (2 * FA_STAGE)

__global__ __launch_bounds__(256, 1)
void flash_attn_mma_kernel(const float* __restrict__ Q, const float* __restrict__ K,
                           const float* __restrict__ V, float* __restrict__ O)
{
    extern __shared__ char smem[];
    const unsigned sb = s2u(smem);
    const int tid = threadIdx.x;
    const int wid = tid >> 5;
    const int lane = tid & 31;
    const int head = blockIdx.y;
    const int bx = (int)gridDim.x - 1 - (int)blockIdx.x;
    const int r0 = bx * 128;
    const int hb = head * HDIM;
    const int rw = r0 + wid * 16;
    const int g = lane >> 2;
    const int t = lane & 3;

#pragma unroll
    for (int u = 0; u < 8; u++) {
        int slot = tid + u * 256;
        int row = slot >> 4;
        int dq = (slot & 15) << 2;
        float4 v = *(const float4*)&Q[(size_t)(r0 + row) * EMB + hb + dq];
        unsigned h01, l01, h23, l23;
        split2(v.x, v.y, h01, l01);
        split2(v.z, v.w, h23, l23);
        unsigned off = (unsigned)(row * FA_ROW + dq * 2);
        STS_V2(sb + off, h01, h23);
        STS_V2(sb + 18432u + off, l01, l23);
    }
    __syncthreads();

    const unsigned a_rl = (unsigned)((lane & 7) + ((lane >> 3) & 1) * 8);
    const unsigned a_by = (unsigned)((lane >> 4) * 16);
    unsigned QH[4][4], QL[4][4];
#pragma unroll
    for (int kc = 0; kc < 4; kc++) {
        unsigned ad = sb + (wid * 16 + a_rl) * FA_ROW + kc * 32 + a_by;
        LDSM_X4(QH[kc][0], QH[kc][1], QH[kc][2], QH[kc][3], ad);
        LDSM_X4(QL[kc][0], QL[kc][1], QL[kc][2], QL[kc][3], ad + 18432u);
    }
    __syncthreads();

    float o[8][4];
#pragma unroll
    for (int j = 0; j < 8; j++)
#pragma unroll
        for (int r = 0; r < 4; r++) o[j][r] = 0.f;
    float m0r = -1e30f, m1r = -1e30f, l0 = 0.f, l1 = 0.f;

    const int ntiles = 2 * bx + 2;
    float4 fk[4], fv[4];

    auto fetchKV = [&](int tI) {
        const int c0 = tI * 64;
#pragma unroll
        for (int u = 0; u < 4; u++) {
            int slot = tid + u * 256;
            int kr = slot >> 4;
            int dq = (slot & 15) << 2;
            fk[u] = *(const float4*)&K[(size_t)(c0 + kr) * EMB + hb + dq];
            fv[u] = *(const float4*)&V[(size_t)(c0 + kr) * EMB + hb + dq];
        }
    };
    auto storeKV = [&](int s) {
        const unsigned base = sb + (unsigned)s * FA_STAGE;
#pragma unroll
        for (int u = 0; u < 4; u++) {
            int slot = tid + u * 256;
            int kr = slot >> 4;
            int dq = (slot & 15) << 2;
            unsigned off = (unsigned)(kr * FA_ROW + dq * 2);
            unsigned h01, l01, h23, l23;
            split2(fk[u].x, fk[u].y, h01, l01);
            split2(fk[u].z, fk[u].w, h23, l23);
            STS_V2(base + off, h01, h23);
            STS_V2(base + FA_TILE + off, l01, l23);
            split2(fv[u].x, fv[u].y, h01, l01);
            split2(fv[u].z, fv[u].w, h23, l23);
            STS_V2(base + 2 * FA_TILE + off, h01, h23);
            STS_V2(base + 3 * FA_TILE + off, l01, l23);
        }
    };

    fetchKV(0);
    storeKV(0);
    if (ntiles > 1) fetchKV(1);

#pragma unroll 1
    for (int c = 0; c < ntiles; c++) {
        __syncthreads();
        if (c + 1 < ntiles) storeKV((c + 1) & 1);
        if (c + 2 < ntiles) fetchKV(c + 2);

        const int c0 = c * 64;
        if (c0 <= rw + 15) {
            const unsigned kb = sb + (unsigned)(c & 1) * FA_STAGE;

            float s[8][4];
#pragma unroll
            for (int j = 0; j < 8; j++)
#pragma unroll
                for (int r = 0; r < 4; r++) s[j][r] = 0.f;

#pragma unroll
            for (int j = 0; j < 8; j++) {
                const unsigned bd = kb + (8 * j + (lane & 7)) * FA_ROW
                                  + ((lane >> 3) & 1) * 16;
#pragma unroll
                for (int kc = 0; kc < 4; kc++) {
                    unsigned bh0, bh1, bl0, bl1;
                    LDSM_X2(bh0, bh1, bd + kc * 32);
                    LDSM_X2(bl0, bl1, bd + kc * 32 + FA_TILE);
                    MMA_BF16(s[j][0], s[j][1], s[j][2], s[j][3],
                             QH[kc][0], QH[kc][1], QH[kc][2], QH[kc][3], bh0, bh1);
                    MMA_BF16(s[j][0], s[j][1], s[j][2], s[j][3],
                             QH[kc][0], QH[kc][1], QH[kc][2], QH[kc][3], bl0, bl1);
                    MMA_BF16(s[j][0], s[j][1], s[j][2], s[j][3],
                             QL[kc][0], QL[kc][1], QL[kc][2], QL[kc][3], bh0, bh1);
                }
            }

            if (c0 + 63 > rw) {
                const int rA = rw + g;
                const int rB = rw + g + 8;
#pragma unroll
                for (int j = 0; j < 8; j++) {
                    int col = c0 + 8 * j + 2 * t;
                    if (col > rA)     s[j][0] = -1e30f;
                    if (col + 1 > rA) s[j][1] = -1e30f;
                    if (col > rB)     s[j][2] = -1e30f;
                    if (col + 1 > rB) s[j][3] = -1e30f;
                }
            }

            float t0 = -1e30f, t1 = -1e30f;
#pragma unroll
            for (int j = 0; j < 8; j++) {
                t0 = fmaxf(t0, fmaxf(s[j][0], s[j][1]));
                t1 = fmaxf(t1, fmaxf(s[j][2], s[j][3]));
            }
            t0 = fmaxf(t0, __shfl_xor_sync(0xffffffff, t0, 1));
            t0 = fmaxf(t0, __shfl_xor_sync(0xffffffff, t0, 2));
            t1 = fmaxf(t1, __shfl_xor_sync(0xffffffff, t1, 1));
            t1 = fmaxf(t1, __shfl_xor_sync(0xffffffff, t1, 2));
            const float mn0 = fmaxf(m0r, t0);
            const float mn1 = fmaxf(m1r, t1);
            const float sc0 = __expf(m0r - mn0);
            const float sc1 = __expf(m1r - mn1);
            float sum0 = 0.f, sum1 = 0.f;
#pragma unroll
            for (int j = 0; j < 8; j++) {
                float p0 = __expf(s[j][0] - mn0);
                float p1 = __expf(s[j][1] - mn0);
                float p2 = __expf(s[j][2] - mn1);
                float p3 = __expf(s[j][3] - mn1);
                s[j][0] = p0; s[j][1] = p1; s[j][2] = p2; s[j][3] = p3;
                sum0 += p0 + p1;
                sum1 += p2 + p3;
            }
            sum0 += __shfl_xor_sync(0xffffffff, sum0, 1);
            sum0 += __shfl_xor_sync(0xffffffff, sum0, 2);
            sum1 += __shfl_xor_sync(0xffffffff, sum1, 1);
            sum1 += __shfl_xor_sync(0xffffffff, sum1, 2);
            l0 = l0 * sc0 + sum0;
            l1 = l1 * sc1 + sum1;
            m0r = mn0; m1r = mn1;
#pragma unroll
            for (int j = 0; j < 8; j++) {
                o[j][0] *= sc0; o[j][1] *= sc0;
                o[j][2] *= sc1; o[j][3] *= sc1;
            }

#pragma unroll
            for (int kc2 = 0; kc2 < 4; kc2++) {
                unsigned ph[4], pl[4];
                split2(s[2 * kc2][0],     s[2 * kc2][1],     ph[0], pl[0]);
                split2(s[2 * kc2][2],     s[2 * kc2][3],     ph[1], pl[1]);
                split2(s[2 * kc2 + 1][0], s[2 * kc2 + 1][1], ph[2], pl[2]);
                split2(s[2 * kc2 + 1][2], s[2 * kc2 + 1][3], ph[3], pl[3]);
                const unsigned vrow = kb + 2 * FA_TILE
                                    + (16 * kc2 + (lane & 15)) * FA_ROW;
#pragma unroll
                for (int j = 0; j < 8; j++) {
                    unsigned v0, v1, w0, w1;
                    LDSM_X2_T(v0, v1, vrow + j * 16);
                    LDSM_X2_T(w0, w1, vrow + j * 16 + FA_TILE);
                    MMA_BF16(o[j][0], o[j][1], o[j][2], o[j][3],
                             ph[0], ph[1], ph[2], ph[3], v0, v1);
                    MMA_BF16(o[j][0], o[j][1], o[j][2], o[j][3],
                             ph[0], ph[1], ph[2], ph[3], w0, w1);
                    MMA_BF16(o[j][0], o[j][1], o[j][2], o[j][3],
                             pl[0], pl[1], pl[2], pl[3], v0, v1);
                }
            }
        }
    }

    const float inv0 = 1.0f / l0;
    const float inv1 = 1.0f / l1;
    const int rA = rw + g;
    const int rB = rw + g + 8;
#pragma unroll
    for (int j = 0; j < 8; j++) {
        const int col = hb + 8 * j + 2 * t;
        float2 oa, ob;
        oa.x = o[j][0] * inv0; oa.y = o[j][1] * inv0;
        ob.x = o[j][2] * inv1; ob.y = o[j][3] * inv1;
        *(float2*)&O[(size_t)rA * EMB + col] = oa;
        *(float2*)&O[(size_t)rB * EMB + col] = ob;
    }
}

// ---------------------------------------------------------------------------
// Launch — fork/join: Q-proj (tensor pipe, now co-residency-sized) overlaps
// the KV SIMT kernel (FMA pipe).
// ---------------------------------------------------------------------------
extern "C" void kernel_launch(void* const* d_in, const int* in_sizes, int n_in,
                              void* d_out, int out_size)
{
    const float* X  = (const float*)d_in[0];
    const float* Wq = (const float*)d_in[1];
    const float* bq = (const float*)d_in[2];
    const float* Wk = (const float*)d_in[3];
    const float* bk = (const float*)d_in[4];
    const float* Wv = (const float*)d_in[5];
    const float* bv = (const float*)d_in[6];
    const float* Wo = (const float*)d_in[7];
    const float* bo = (const float*)d_in[8];
    float* out = (float*)d_out;

    void *pQ, *pK, *pV, *pO;
    cudaGetSymbolAddress(&pQ, g_Q);
    cudaGetSymbolAddress(&pK, g_K);
    cudaGetSymbolAddress(&pV, g_V);
    cudaGetSymbolAddress(&pO, g_O);
    float* Qb = (float*)pQ;
    float* Kb = (float*)pK;
    float* Vb = (float*)pV;
    float* Ob = (float*)pO;

    cudaFuncSetAttribute(gemm_mma_kernel,
                         cudaFuncAttributeMaxDynamicSharedMemorySize, GEMM_SMEM);
    cudaFuncSetAttribute(flash_attn_mma_kernel,
                         cudaFuncAttributeMaxDynamicSharedMemorySize, FA_SMEM);

    dim3 gg(EMB / 64, SEQ / 128);   // 32 x 16 = 512 CTAs (tile 128x64)

    cudaStream_t side;
    cudaStreamCreateWithFlags(&side, cudaStreamNonBlocking);
    cudaEvent_t evFork, evJoin;
    cudaEventCreateWithFlags(&evFork, cudaEventDisableTiming);
    cudaEventCreateWithFlags(&evJoin, cudaEventDisableTiming);

    cudaEventRecord(evFork, 0);
    cudaStreamWaitEvent(side, evFork, 0);

    // Q projection on side stream (tensor pipe) — overlaps KV (FMA pipe)
    gemm_mma_kernel<<<gg, 256, GEMM_SMEM, side>>>(X, Wq, bq, Qb, SCALING);

    // K + V projections with fused quantize on main stream
    kv_gemm_quant_kernel<<<dim3(EMB / 128, SEQ / 128, 2), 256>>>(
        X, Wk, bk, Kb, Wv, bv, Vb);

    cudaEventRecord(evJoin, side);
    cudaStreamWaitEvent(0, evJoin, 0);

    flash_attn_mma_kernel<<<dim3(SEQ / 128, NHEAD), 256, FA_SMEM>>>(Qb, Kb, Vb, Ob);

    // Output projection: bf16x3 mma (bitwise-identical re-tiling)
    gemm_mma_kernel<<<gg, 256, GEMM_SMEM>>>(Ob, Wo, bo, out, 1.0f);

    cudaEventDestroy(evFork);
    cudaEventDestroy(evJoin);
    cudaStreamDestroy(side);
}